// round 13
// baseline (speedup 1.0000x reference)
#include <cuda_runtime.h>
#include <math.h>

#define NBATCH 16
#define LPAD 1280
#define LIN 1250
#define DM 64
#define NH 4
#define DH 16
#define NR 4        // hash rounds
#define BSZ 64      // bucket chunk size
#define NB 20       // buckets per round
#define NCH 80      // NR*NB chunks
#define BHH 64      // NBATCH*NH
#define MR 20480    // NBATCH*LPAD
#define FF 256

typedef unsigned long long ull;

__device__ __forceinline__ ull pack2(float lo, float hi){
  ull r; asm("mov.b64 %0,{%1,%2};" : "=l"(r) : "f"(lo), "f"(hi)); return r;
}
__device__ __forceinline__ void unpack2(ull a, float& lo, float& hi){
  asm("mov.b64 {%0,%1},%2;" : "=f"(lo), "=f"(hi) : "l"(a));
}
__device__ __forceinline__ void fma2(ull& d, ull a, ull b){
  asm("fma.rn.f32x2 %0,%1,%2,%0;" : "+l"(d) : "l"(a), "l"(b));
}
__device__ __forceinline__ void mul2(ull& d, ull a, ull b){
  asm("mul.rn.f32x2 %0,%1,%2;" : "=l"(d) : "l"(a), "l"(b));
}
__device__ __forceinline__ float hsum2(ull a){
  float lo, hi; unpack2(a, lo, hi); return lo + hi;
}

// ---------------- scratch (device globals; no allocation allowed) ----------------
__device__ float g_x1[MR*DM];
__device__ float g_x2[MR*DM];
__device__ float g_qk[BHH*LPAD*DH];
__device__ float g_v [BHH*LPAD*DH];
__device__ unsigned char g_bkt[BHH*NR*LPAD];
__device__ int   g_cnt[BHH*NR*8*NB];
__device__ short g_sj [BHH*NR*LPAD];
__device__ float g_o  [BHH*NR*LPAD*DH];
__device__ float g_lse[BHH*NR*LPAD];
__device__ float g_ffh[MR*FF];

// ---------------- embed: x = pad(wave^T) @ in_w + in_b ----------------
__global__ void k_embed(const float* __restrict__ wave, const float* __restrict__ in_w,
                        const float* __restrict__ in_b, float* __restrict__ x1,
                        float* __restrict__ x2){
  int gid = blockIdx.x*256 + threadIdx.x;       // 16*1280*64 total
  int d = gid & 63;
  int t = (gid >> 6) % LPAD;
  int b = gid / (LPAD*64);
  float val = in_b[d];
  if (t < LIN)
    val += wave[b*2*LIN + t]*in_w[d] + wave[b*2*LIN + LIN + t]*in_w[64+d];
  x1[gid] = val; x2[gid] = val;
}

__device__ __forceinline__ float gelu_f(float x){
  return 0.5f*x*(1.0f + erff(x*0.7071067811865476f));
}

// In-shared-tile layernorm, 64-row tile [68] stride: 4 threads/row, 16 cols each.
__device__ __forceinline__ void ln_tile64(float (*Xs)[68], int tid,
                                          const float* __restrict__ g,
                                          const float* __restrict__ b){
  int r = tid >> 2, q = tid & 3;
  float vals[16];
  float4* xp = (float4*)&Xs[r][q*16];
  #pragma unroll
  for (int i=0;i<4;i++){
    float4 f4 = xp[i];
    vals[4*i]=f4.x; vals[4*i+1]=f4.y; vals[4*i+2]=f4.z; vals[4*i+3]=f4.w;
  }
  float s = 0.f;
  #pragma unroll
  for (int f=0;f<16;f++) s += vals[f];
  s += __shfl_xor_sync(0xffffffffu, s, 1);
  s += __shfl_xor_sync(0xffffffffu, s, 2);
  float mean = s * (1.0f/64.0f);
  float sq = 0.f;
  #pragma unroll
  for (int f=0;f<16;f++){ float d = vals[f]-mean; sq += d*d; }
  sq += __shfl_xor_sync(0xffffffffu, sq, 1);
  sq += __shfl_xor_sync(0xffffffffu, sq, 2);
  float inv = rsqrtf(sq*(1.0f/64.0f) + 1e-5f);
  #pragma unroll
  for (int i=0;i<4;i++){
    float4 gg = ((const float4*)(g + q*16))[i];
    float4 bb = ((const float4*)(b + q*16))[i];
    float4 o;
    o.x = (vals[4*i]  -mean)*inv*gg.x + bb.x;
    o.y = (vals[4*i+1]-mean)*inv*gg.y + bb.y;
    o.z = (vals[4*i+2]-mean)*inv*gg.z + bb.z;
    o.w = (vals[4*i+3]-mean)*inv*gg.w + bb.w;
    xp[i] = o;
  }
}

// ---------------- fused LN1 + qk/v GEMM (64x64 tiles, head-split output) ----------------
__global__ __launch_bounds__(256) void k_lnqkv(const float* __restrict__ X,
                           const float* __restrict__ lg, const float* __restrict__ lb,
                           const float* __restrict__ Wq,
                           const float* __restrict__ Wv, float* __restrict__ qk,
                           float* __restrict__ v){
  __shared__ float Xs[64][68];
  __shared__ float Wqs[64][68];
  __shared__ float Wvs[64][68];
  int tid = threadIdx.x;
  int row0 = blockIdx.x*64;
  int tx = tid & 15, ty = tid >> 4;
  { int r = tid & 63, q = tid >> 6;
    const float4* src = (const float4*)(X + (size_t)(row0+r)*64) + q*4;
    float4* dst = (float4*)&Xs[r][q*16];
    dst[0]=src[0]; dst[1]=src[1]; dst[2]=src[2]; dst[3]=src[3]; }
  { int k = tid & 63, q = tid >> 6;
    const float* wr = Wq + (size_t)k*64 + q*16;
    const float* vr = Wv + (size_t)k*64 + q*16;
    #pragma unroll
    for (int i=0;i<4;i++){
      float4 w = ((const float4*)wr)[i];
      float4 wv2 = ((const float4*)vr)[i];
      int c = q*16 + 4*i;
      Wqs[c+0][k]=w.x; Wqs[c+1][k]=w.y; Wqs[c+2][k]=w.z; Wqs[c+3][k]=w.w;
      Wvs[c+0][k]=wv2.x; Wvs[c+1][k]=wv2.y; Wvs[c+2][k]=wv2.z; Wvs[c+3][k]=wv2.w;
    } }
  __syncthreads();
  ln_tile64(Xs, tid, lg, lb);
  __syncthreads();
  ull accq[4][4], accv[4][4];
  #pragma unroll
  for (int i=0;i<4;i++)
    #pragma unroll
    for (int j=0;j<4;j++){ accq[i][j]=0ull; accv[i][j]=0ull; }
  #pragma unroll
  for (int kq=0; kq<16; kq++){
    ull xv[4][2], wq2[4][2], wv2[4][2];
    #pragma unroll
    for (int i=0;i<4;i++){
      ulonglong2 t = *(const ulonglong2*)&Xs[4*ty+i][kq*4];
      xv[i][0]=t.x; xv[i][1]=t.y;
    }
    #pragma unroll
    for (int j=0;j<4;j++){
      ulonglong2 a = *(const ulonglong2*)&Wqs[4*tx+j][kq*4];
      wq2[j][0]=a.x; wq2[j][1]=a.y;
      ulonglong2 b = *(const ulonglong2*)&Wvs[4*tx+j][kq*4];
      wv2[j][0]=b.x; wv2[j][1]=b.y;
    }
    #pragma unroll
    for (int i=0;i<4;i++)
      #pragma unroll
      for (int j=0;j<4;j++){
        fma2(accq[i][j], xv[i][0], wq2[j][0]);
        fma2(accq[i][j], xv[i][1], wq2[j][1]);
        fma2(accv[i][j], xv[i][0], wv2[j][0]);
        fma2(accv[i][j], xv[i][1], wv2[j][1]);
      }
  }
  int head = tx >> 2, d0 = 4*(tx & 3);
  #pragma unroll
  for (int i=0;i<4;i++){
    int m = row0 + 4*ty + i;
    int b = m / LPAD, t = m % LPAD;
    size_t base = ((size_t)(b*NH + head)*LPAD + t)*DH + d0;
    float4 oq, ov;
    oq.x=hsum2(accq[i][0]); oq.y=hsum2(accq[i][1]); oq.z=hsum2(accq[i][2]); oq.w=hsum2(accq[i][3]);
    ov.x=hsum2(accv[i][0]); ov.y=hsum2(accv[i][1]); ov.z=hsum2(accv[i][2]); ov.w=hsum2(accv[i][3]);
    *(float4*)(qk + base) = oq;
    *(float4*)(v  + base) = ov;
  }
}

// ---------------- fused combine + output GEMM + residual ----------------
__global__ __launch_bounds__(256) void k_wo(const float* __restrict__ o,
                       const float* __restrict__ lse,
                       const float* __restrict__ W,
                       const float* __restrict__ bias, float* __restrict__ Y){
  __shared__ float Xs[64][68];
  __shared__ float Ws[64][68];
  int tid = threadIdx.x;
  int row0 = blockIdx.x*64;
  int tx = tid & 15, ty = tid >> 4;
  { int k = tid & 63, q = tid >> 6;
    const float* wr = W + (size_t)k*64 + q*16;
    #pragma unroll
    for (int i=0;i<4;i++){
      float4 w = ((const float4*)wr)[i];
      int c = q*16 + 4*i;
      Ws[c+0][k]=w.x; Ws[c+1][k]=w.y; Ws[c+2][k]=w.z; Ws[c+3][k]=w.w;
    } }
  { int r = tid & 63, h = tid >> 6;
    int m = row0 + r; int b = m / LPAD, t = m % LPAD;
    int bh = b*NH + h;
    float ls[NR];
    #pragma unroll
    for (int rr=0;rr<NR;rr++) ls[rr] = lse[(size_t)(bh*NR+rr)*LPAD + t];
    float mx = fmaxf(fmaxf(ls[0],ls[1]), fmaxf(ls[2],ls[3]));
    float w[NR], s=0.f;
    #pragma unroll
    for (int rr=0;rr<NR;rr++){ w[rr]=__expf(ls[rr]-mx); s+=w[rr]; }
    float invs = 1.f/s;
    #pragma unroll
    for (int rr=0;rr<NR;rr++) w[rr] *= invs;
    const float* ob = o + ((size_t)(bh*NR)*LPAD + t)*DH;
    #pragma unroll
    for (int i=0;i<4;i++){
      float4 a = make_float4(0.f,0.f,0.f,0.f);
      #pragma unroll
      for (int rr=0;rr<NR;rr++){
        float4 ov = *(const float4*)(ob + (size_t)rr*LPAD*DH + 4*i);
        a.x += w[rr]*ov.x; a.y += w[rr]*ov.y; a.z += w[rr]*ov.z; a.w += w[rr]*ov.w;
      }
      *(float4*)&Xs[r][h*16 + 4*i] = a;
    } }
  __syncthreads();
  ull acc[4][4];
  #pragma unroll
  for (int i=0;i<4;i++)
    #pragma unroll
    for (int j=0;j<4;j++) acc[i][j]=0ull;
  #pragma unroll
  for (int kq=0; kq<16; kq++){
    ull xv[4][2], wv[4][2];
    #pragma unroll
    for (int i=0;i<4;i++){
      ulonglong2 t = *(const ulonglong2*)&Xs[4*ty+i][kq*4];
      xv[i][0]=t.x; xv[i][1]=t.y;
    }
    #pragma unroll
    for (int j=0;j<4;j++){
      ulonglong2 t = *(const ulonglong2*)&Ws[4*tx+j][kq*4];
      wv[j][0]=t.x; wv[j][1]=t.y;
    }
    #pragma unroll
    for (int i=0;i<4;i++)
      #pragma unroll
      for (int j=0;j<4;j++){
        fma2(acc[i][j], xv[i][0], wv[j][0]);
        fma2(acc[i][j], xv[i][1], wv[j][1]);
      }
  }
  float4 b4 = ((const float4*)bias)[tx];
  #pragma unroll
  for (int i=0;i<4;i++){
    int row = row0 + 4*ty + i;
    float4* yp = (float4*)(Y + (size_t)row*64);
    float4 prev = yp[tx];
    float4 oo;
    oo.x = hsum2(acc[i][0]) + b4.x + prev.x;
    oo.y = hsum2(acc[i][1]) + b4.y + prev.y;
    oo.z = hsum2(acc[i][2]) + b4.z + prev.z;
    oo.w = hsum2(acc[i][3]) + b4.w + prev.w;
    yp[tx] = oo;
  }
}

// ---------------- FF part 1: LN2 + X@W1 + gelu (64x64 tiles, f32x2, proven body) -------
__global__ __launch_bounds__(256) void k_ff1(const float* __restrict__ X,
                       const float* __restrict__ lg, const float* __restrict__ lb,
                       const float* __restrict__ W1, const float* __restrict__ b1,
                       float* __restrict__ H){
  __shared__ float Xs[64][68];
  __shared__ float Ws[64][68];
  int tid = threadIdx.x;
  int row0 = blockIdx.x*64;
  int col0 = blockIdx.y*64;
  int tx = tid & 15, ty = tid >> 4;
  { int r = tid & 63, q = tid >> 6;
    const float4* src = (const float4*)(X + (size_t)(row0+r)*64) + q*4;
    float4* dst = (float4*)&Xs[r][q*16];
    dst[0]=src[0]; dst[1]=src[1]; dst[2]=src[2]; dst[3]=src[3]; }
  { int k = tid & 63, q = tid >> 6;
    const float* wr = W1 + (size_t)k*FF + col0 + q*16;
    #pragma unroll
    for (int i=0;i<4;i++){
      float4 w = ((const float4*)wr)[i];
      int c = q*16 + 4*i;
      Ws[c+0][k]=w.x; Ws[c+1][k]=w.y; Ws[c+2][k]=w.z; Ws[c+3][k]=w.w;
    } }
  __syncthreads();
  ln_tile64(Xs, tid, lg, lb);
  __syncthreads();
  ull acc[4][4];
  #pragma unroll
  for (int i=0;i<4;i++)
    #pragma unroll
    for (int j=0;j<4;j++) acc[i][j]=0ull;
  #pragma unroll
  for (int kq=0; kq<16; kq++){
    ull xv[4][2], wv[4][2];
    #pragma unroll
    for (int i=0;i<4;i++){
      ulonglong2 t = *(const ulonglong2*)&Xs[4*ty+i][kq*4];
      xv[i][0]=t.x; xv[i][1]=t.y;
    }
    #pragma unroll
    for (int j=0;j<4;j++){
      ulonglong2 t = *(const ulonglong2*)&Ws[4*tx+j][kq*4];
      wv[j][0]=t.x; wv[j][1]=t.y;
    }
    #pragma unroll
    for (int i=0;i<4;i++)
      #pragma unroll
      for (int j=0;j<4;j++){
        fma2(acc[i][j], xv[i][0], wv[j][0]);
        fma2(acc[i][j], xv[i][1], wv[j][1]);
      }
  }
  float4 b4 = ((const float4*)(b1 + col0))[tx];
  #pragma unroll
  for (int i=0;i<4;i++){
    int row = row0 + 4*ty + i;
    float4 oo;
    oo.x = gelu_f(hsum2(acc[i][0]) + b4.x);
    oo.y = gelu_f(hsum2(acc[i][1]) + b4.y);
    oo.z = gelu_f(hsum2(acc[i][2]) + b4.z);
    oo.w = gelu_f(hsum2(acc[i][3]) + b4.w);
    ((float4*)(H + (size_t)row*FF + col0))[tx] = oo;
  }
}

// ---------------- FF part 2: H@W2 + residual (K=256, 64x64 tiles, f32x2) ---------------
__global__ __launch_bounds__(256) void k_ff2(const float* __restrict__ H,
                       const float* __restrict__ W2, const float* __restrict__ b2,
                       float* __restrict__ Y){
  __shared__ float Xs[64][68];
  __shared__ float Ws[64][68];
  int tid = threadIdx.x;
  int row0 = blockIdx.x*64;
  int tx = tid & 15, ty = tid >> 4;
  ull acc[4][4];
  #pragma unroll
  for (int i=0;i<4;i++)
    #pragma unroll
    for (int j=0;j<4;j++) acc[i][j]=0ull;
  for (int kc=0; kc<4; kc++){
    __syncthreads();
    { int r = tid & 63, q = tid >> 6;
      const float4* src = (const float4*)(H + (size_t)(row0+r)*FF + kc*64) + q*4;
      float4* dst = (float4*)&Xs[r][q*16];
      dst[0]=src[0]; dst[1]=src[1]; dst[2]=src[2]; dst[3]=src[3]; }
    { int k = tid & 63, q = tid >> 6;
      const float* wr = W2 + (size_t)(kc*64+k)*64 + q*16;
      #pragma unroll
      for (int i=0;i<4;i++){
        float4 w = ((const float4*)wr)[i];
        int c = q*16 + 4*i;
        Ws[c+0][k]=w.x; Ws[c+1][k]=w.y; Ws[c+2][k]=w.z; Ws[c+3][k]=w.w;
      } }
    __syncthreads();
    #pragma unroll
    for (int kq=0; kq<16; kq++){
      ull xv[4][2], wv[4][2];
      #pragma unroll
      for (int i=0;i<4;i++){
        ulonglong2 t = *(const ulonglong2*)&Xs[4*ty+i][kq*4];
        xv[i][0]=t.x; xv[i][1]=t.y;
      }
      #pragma unroll
      for (int j=0;j<4;j++){
        ulonglong2 t = *(const ulonglong2*)&Ws[4*tx+j][kq*4];
        wv[j][0]=t.x; wv[j][1]=t.y;
      }
      #pragma unroll
      for (int i=0;i<4;i++)
        #pragma unroll
        for (int j=0;j<4;j++){
          fma2(acc[i][j], xv[i][0], wv[j][0]);
          fma2(acc[i][j], xv[i][1], wv[j][1]);
        }
    }
  }
  float4 b4 = ((const float4*)b2)[tx];
  #pragma unroll
  for (int i=0;i<4;i++){
    int row = row0 + 4*ty + i;
    float4* yp = (float4*)(Y + (size_t)row*64);
    float4 prev = yp[tx];
    float4 oo;
    oo.x = hsum2(acc[i][0]) + b4.x + prev.x;
    oo.y = hsum2(acc[i][1]) + b4.y + prev.y;
    oo.z = hsum2(acc[i][2]) + b4.z + prev.z;
    oo.w = hsum2(acc[i][3]) + b4.w + prev.w;
    yp[tx] = oo;
  }
}

// ---------------- LSH hashing + per-segment histogram (fused, proven) ----------------
__global__ void k_hashcount(const float* __restrict__ qk, const float* __restrict__ rot,
                            unsigned char* __restrict__ bkt, int* __restrict__ cnt){
  __shared__ float rs[640];                      // rot (16,4,10)
  __shared__ int c[NR][NB];
  int tid = threadIdx.x;                         // 160
  int seg = blockIdx.x, bh = blockIdx.y;
  for (int i=tid;i<640;i+=160) rs[i]=rot[i];
  if (tid < NR*NB) ((int*)c)[tid] = 0;
  __syncthreads();
  int t = seg*160 + tid;
  const float4* qr = reinterpret_cast<const float4*>(qk + ((size_t)bh*LPAD + t)*DH);
  float q[16];
  #pragma unroll
  for (int i=0;i<4;i++){ float4 f4=qr[i]; q[4*i]=f4.x; q[4*i+1]=f4.y; q[4*i+2]=f4.z; q[4*i+3]=f4.w; }
  #pragma unroll
  for (int r=0;r<NR;r++){
    float p[10];
    #pragma unroll
    for (int i=0;i<10;i++){
      float s=0.f;
      #pragma unroll
      for (int f=0;f<16;f++) s += q[f]*rs[f*40 + r*10 + i];
      p[i]=s;
    }
    float best=-3.402823e38f; int bi=0;
    #pragma unroll
    for (int idx=0; idx<20; idx++){
      float val = (idx<10)? p[idx] : -p[idx-10];
      if (val>best){best=val;bi=idx;}           // first-max tie-break like jnp.argmax
    }
    bkt[((size_t)bh*NR + r)*LPAD + t] = (unsigned char)bi;
    atomicAdd(&c[r][bi], 1);
  }
  __syncthreads();
  if (tid < NR*NB){
    int r = tid / NB, b = tid % NB;
    cnt[((size_t)((bh*NR+r)*8 + seg))*NB + b] = c[r][b];
  }
}

// ---------------- fused prefix scan + stable scatter (uchar4 loads) ----------------
__global__ __launch_bounds__(640) void k_psort(const int* __restrict__ cnt,
                         const unsigned char* __restrict__ bkt,
                         short* __restrict__ sj){
  __shared__ int ws[20];
  __shared__ int offs[32][NB];                   // [(r,seg)][b]
  int bh = blockIdx.x;
  int i = threadIdx.x;                           // 640
  int r = i/160, b = (i%160)/8, seg = i%8;       // scan order (r,b,seg)
  int idx = ((bh*NR + r)*8 + seg)*NB + b;
  int v = cnt[idx];
  int lane = i & 31, w = i >> 5;
  int s = v;
  #pragma unroll
  for (int o=1;o<32;o<<=1){ int t=__shfl_up_sync(0xffffffffu, s, o); if (lane>=o) s+=t; }
  if (lane==31) ws[w]=s;
  __syncthreads();
  if (i < 32){
    int t = (i<20)? ws[i] : 0;
    #pragma unroll
    for (int o=1;o<32;o<<=1){ int u=__shfl_up_sync(0xffffffffu, t, o); if (i>=o) t+=u; }
    if (i<20) ws[i]=t;
  }
  __syncthreads();
  int base = (w>0)? ws[w-1] : 0;
  offs[r*8+seg][b] = base + s - v;
  __syncthreads();
  if (i < 32){
    int r2 = i >> 3, s2 = i & 7;
    const uchar4* p4 = (const uchar4*)(bkt + ((size_t)bh*NR + r2)*LPAD + s2*160);
    short* sjb = sj + (size_t)bh*NR*LPAD;
    int basej = r2*LPAD + s2*160;
    int* cc = offs[i];
    #pragma unroll 2
    for (int k=0;k<40;k++){
      uchar4 u = p4[k];
      int s3;
      s3 = cc[u.x]++; sjb[s3] = (short)(basej + 4*k);
      s3 = cc[u.y]++; sjb[s3] = (short)(basej + 4*k + 1);
      s3 = cc[u.z]++; sjb[s3] = (short)(basej + 4*k + 2);
      s3 = cc[u.w]++; sjb[s3] = (short)(basej + 4*k + 3);
    }
  }
}

// ---------------- chunked LSH attention, flash softmax, split-K x2 (proven R8) ---------
__global__ __launch_bounds__(128) void k_attn(const float* __restrict__ qk,
                       const float* __restrict__ v,
                       const short* __restrict__ sj, float* __restrict__ o,
                       float* __restrict__ lse){
  __shared__ float Ks[128][16];
  __shared__ float Vs[128][16];
  __shared__ int   tks[128];
  __shared__ float Pm[64], Pl[64];
  __shared__ float Pacc[64][16];
  int c = blockIdx.x, bh = blockIdx.y, tid = threadIdx.x;  // 128 threads
  int qi = tid & 63, half = tid >> 6;
  const short* sjb = sj + (size_t)bh*NR*LPAD;
  int jq = sjb[c*BSZ + qi];
  int tq = jq % LPAD, rq = jq / LPAD;
  ull qv[8];
  { const ulonglong2* qr = reinterpret_cast<const ulonglong2*>(qk + ((size_t)bh*LPAD + tq)*DH);
    #pragma unroll
    for (int i=0;i<4;i++){ ulonglong2 u=qr[i]; qv[2*i]=u.x; qv[2*i+1]=u.y; } }
  int prev = (c + NCH - 1) % NCH;
  { int kk = tid;
    int cc = (kk<64)? c : prev;
    int jk = sjb[cc*BSZ + (kk&63)];
    int tk = jk % LPAD;
    float kvv[16];
    { const float4* kr = reinterpret_cast<const float4*>(qk + ((size_t)bh*LPAD + tk)*DH);
      #pragma unroll
      for (int i=0;i<4;i++){ float4 f4=kr[i]; kvv[4*i]=f4.x; kvv[4*i+1]=f4.y; kvv[4*i+2]=f4.z; kvv[4*i+3]=f4.w; } }
    float ss=0.f;
    #pragma unroll
    for (int f=0;f<16;f++) ss += kvv[f]*kvv[f];
    float inv = 1.0f / fmaxf(sqrtf(ss), 1e-12f);
    float4* kd = (float4*)&Ks[kk][0];
    #pragma unroll
    for (int i=0;i<4;i++){
      float4 f4; f4.x=kvv[4*i]*inv; f4.y=kvv[4*i+1]*inv; f4.z=kvv[4*i+2]*inv; f4.w=kvv[4*i+3]*inv;
      kd[i]=f4;
    }
    { const float4* vr = reinterpret_cast<const float4*>(v + ((size_t)bh*LPAD + tk)*DH);
      float4* vd = (float4*)&Vs[kk][0];
      #pragma unroll
      for (int i=0;i<4;i++) vd[i]=vr[i];
    }
    tks[kk]=tk;
  }
  __syncthreads();
  float m=-3.0e38f, l=0.f;
  ull acc2[8];
  #pragma unroll
  for (int f=0;f<8;f++) acc2[f]=0ull;
  int jbase = half << 6;
  #pragma unroll 2
  for (int jj=0;jj<64;jj++){
    int j = jbase + jj;
    const ulonglong2* kr = (const ulonglong2*)&Ks[j][0];
    ull d2 = 0ull;
    #pragma unroll
    for (int i=0;i<4;i++){
      ulonglong2 u = kr[i];
      fma2(d2, qv[2*i],   u.x);
      fma2(d2, qv[2*i+1], u.y);
    }
    float d = hsum2(d2) * 0.25f;                 // DH^-0.5
    if (tks[j]==tq) d = -50000.0f;               // SELF_ATTN_VAL
    if (d>m){
      float sc=__expf(m-d);
      l*=sc;
      ull sc2 = pack2(sc,sc);
      #pragma unroll
      for (int f=0;f<8;f++) mul2(acc2[f], acc2[f], sc2);
      m=d;
    }
    float p=__expf(d-m);
    l += p;
    ull p2 = pack2(p,p);
    const ulonglong2* vr = (const ulonglong2*)&Vs[j][0];
    #pragma unroll
    for (int i=0;i<4;i++){
      ulonglong2 u = vr[i];
      fma2(acc2[2*i],   p2, u.x);
      fma2(acc2[2*i+1], p2, u.y);
    }
  }
  if (half){
    Pm[qi]=m; Pl[qi]=l;
    float tmp[16];
    #pragma unroll
    for (int f=0;f<8;f++) unpack2(acc2[f], tmp[2*f], tmp[2*f+1]);
    float4* pa = (float4*)Pacc[qi];
    #pragma unroll
    for (int i=0;i<4;i++){
      float4 f4; f4.x=tmp[4*i]; f4.y=tmp[4*i+1]; f4.z=tmp[4*i+2]; f4.w=tmp[4*i+3];
      pa[i]=f4;
    }
  }
  __syncthreads();
  if (!half){
    float m2 = Pm[qi], l2 = Pl[qi];
    float M = fmaxf(m, m2);
    float s1 = __expf(m - M), s2 = __expf(m2 - M);
    float L = l*s1 + l2*s2;
    float invl = 1.0f/L;
    float out[16];
    #pragma unroll
    for (int f=0;f<8;f++) unpack2(acc2[f], out[2*f], out[2*f+1]);
    const float4* pa = (const float4*)Pacc[qi];
    float4* op = (float4*)(o + ((size_t)(bh*NR + rq)*LPAD + tq)*DH);  // scatter == undo_sort
    #pragma unroll
    for (int i=0;i<4;i++){
      float4 p = pa[i];
      float4 f4;
      f4.x = (out[4*i+0]*s1 + p.x*s2)*invl;
      f4.y = (out[4*i+1]*s1 + p.y*s2)*invl;
      f4.z = (out[4*i+2]*s1 + p.z*s2)*invl;
      f4.w = (out[4*i+3]*s1 + p.w*s2)*invl;
      op[i]=f4;
    }
    lse[(size_t)(bh*NR+rq)*LPAD + tq] = M + logf(L);
  }
}

// ---------------- final: y = ((x1+x2)*0.5) @ out_w + out_b, trim to 1250 ----------------
__global__ void k_final(const float* __restrict__ x1, const float* __restrict__ x2,
                        const float* __restrict__ ow, const float* __restrict__ ob,
                        float* __restrict__ y){
  int row  = blockIdx.x*4 + (threadIdx.x>>5);    // 16*1250 rows
  int lane = threadIdx.x & 31;
  int b = row / LIN, t = row % LIN;
  size_t base = ((size_t)b*LPAD + t)*DM;
  float s = (x1[base+lane]+x2[base+lane])*0.5f*ow[lane]
          + (x1[base+lane+32]+x2[base+lane+32])*0.5f*ow[lane+32];
  #pragma unroll
  for (int o2=16;o2>0;o2>>=1) s += __shfl_xor_sync(0xffffffffu, s, o2);
  if (lane==0) y[row] = s + ob[0];
}

// ---------------- host launcher ----------------
extern "C" void kernel_launch(void* const* d_in, const int* in_sizes, int n_in,
                              void* d_out, int out_size){
  const float* wave  = (const float*)d_in[0];
  const float* in_w  = (const float*)d_in[1];
  const float* in_b  = (const float*)d_in[2];
  const float* ln1_g = (const float*)d_in[3];
  const float* ln1_b = (const float*)d_in[4];
  const float* wqk   = (const float*)d_in[5];
  const float* wv    = (const float*)d_in[6];
  const float* wo_w  = (const float*)d_in[7];
  const float* wo_b  = (const float*)d_in[8];
  const float* rot   = (const float*)d_in[9];
  const float* ln2_g = (const float*)d_in[10];
  const float* ln2_b = (const float*)d_in[11];
  const float* w1    = (const float*)d_in[12];
  const float* b1    = (const float*)d_in[13];
  const float* w2    = (const float*)d_in[14];
  const float* b2    = (const float*)d_in[15];
  const float* out_w = (const float*)d_in[16];
  const float* out_b = (const float*)d_in[17];

  float *x1,*x2,*qkp,*vp,*op,*lsp,*ffp;
  unsigned char* bktp; int *cntp; short* sjp;
  cudaGetSymbolAddress((void**)&x1,  g_x1);
  cudaGetSymbolAddress((void**)&x2,  g_x2);
  cudaGetSymbolAddress((void**)&qkp, g_qk);
  cudaGetSymbolAddress((void**)&vp,  g_v);
  cudaGetSymbolAddress((void**)&bktp,g_bkt);
  cudaGetSymbolAddress((void**)&cntp,g_cnt);
  cudaGetSymbolAddress((void**)&sjp, g_sj);
  cudaGetSymbolAddress((void**)&op,  g_o);
  cudaGetSymbolAddress((void**)&lsp, g_lse);
  cudaGetSymbolAddress((void**)&ffp, g_ffh);

  k_embed<<<5120,256>>>(wave, in_w, in_b, x1, x2);

  for (int i=0;i<4;i++){
    k_lnqkv<<<320,256>>>(x2, ln1_g+i*64, ln1_b+i*64, wqk+i*4096, wv+i*4096, qkp, vp);
    k_hashcount<<<dim3(8,64),160>>>(qkp, rot+i*640, bktp, cntp);
    k_psort<<<64,640>>>(cntp, bktp, sjp);
    k_attn<<<dim3(80,64),128>>>(qkp, vp, sjp, op, lsp);
    k_wo<<<320,256>>>(op, lsp, wo_w+i*4096, wo_b+i*64, x1);
    k_ff1<<<dim3(320,4),256>>>(x1, ln2_g+i*64, ln2_b+i*64, w1+i*16384, b1+i*256, ffp);
    k_ff2<<<320,256>>>(ffp, w2+i*16384, b2+i*64, x2);
  }

  k_final<<<5000,128>>>(x1, x2, out_w, out_b, (float*)d_out);
}

// round 14
// speedup vs baseline: 1.2319x; 1.2319x over previous
#include <cuda_runtime.h>
#include <math.h>

#define NBATCH 16
#define LPAD 1280
#define LIN 1250
#define DM 64
#define NH 4
#define DH 16
#define NR 4        // hash rounds
#define BSZ 64      // bucket chunk size
#define NB 20       // buckets per round
#define NCH 80      // NR*NB chunks
#define BHH 64      // NBATCH*NH
#define MR 20480    // NBATCH*LPAD
#define FF 256

typedef unsigned long long ull;

__device__ __forceinline__ ull pack2(float lo, float hi){
  ull r; asm("mov.b64 %0,{%1,%2};" : "=l"(r) : "f"(lo), "f"(hi)); return r;
}
__device__ __forceinline__ void unpack2(ull a, float& lo, float& hi){
  asm("mov.b64 {%0,%1},%2;" : "=f"(lo), "=f"(hi) : "l"(a));
}
__device__ __forceinline__ void fma2(ull& d, ull a, ull b){
  asm("fma.rn.f32x2 %0,%1,%2,%0;" : "+l"(d) : "l"(a), "l"(b));
}
__device__ __forceinline__ void mul2(ull& d, ull a, ull b){
  asm("mul.rn.f32x2 %0,%1,%2;" : "=l"(d) : "l"(a), "l"(b));
}
__device__ __forceinline__ float hsum2(ull a){
  float lo, hi; unpack2(a, lo, hi); return lo + hi;
}

// ---------------- scratch (device globals; no allocation allowed) ----------------
__device__ float g_x1[MR*DM];
__device__ float g_x2[MR*DM];
__device__ float g_qk[BHH*LPAD*DH];
__device__ float g_v [BHH*LPAD*DH];
__device__ unsigned char g_bkt[BHH*NR*LPAD];
__device__ int   g_cnt[BHH*NR*8*NB];
__device__ short g_sj [BHH*NR*LPAD];
__device__ float g_o  [BHH*NR*LPAD*DH];
__device__ float g_lse[BHH*NR*LPAD];
__device__ float g_ffh[MR*FF];

// ---------------- embed: x = pad(wave^T) @ in_w + in_b ----------------
__global__ void k_embed(const float* __restrict__ wave, const float* __restrict__ in_w,
                        const float* __restrict__ in_b, float* __restrict__ x1,
                        float* __restrict__ x2){
  int gid = blockIdx.x*256 + threadIdx.x;       // 16*1280*64 total
  int d = gid & 63;
  int t = (gid >> 6) % LPAD;
  int b = gid / (LPAD*64);
  float val = in_b[d];
  if (t < LIN)
    val += wave[b*2*LIN + t]*in_w[d] + wave[b*2*LIN + LIN + t]*in_w[64+d];
  x1[gid] = val; x2[gid] = val;
}

__device__ __forceinline__ float gelu_f(float x){
  return 0.5f*x*(1.0f + erff(x*0.7071067811865476f));
}

// In-shared-tile layernorm, 32-row tile [68] stride: 8 threads/row, 8 cols each.
__device__ __forceinline__ void ln_tile32(float (*Xs)[68], int tid,
                                          const float* __restrict__ g,
                                          const float* __restrict__ b){
  int r = tid >> 3, q = tid & 7;
  float4* xp = (float4*)&Xs[r][q*8];
  float4 a0 = xp[0], a1 = xp[1];
  float s = a0.x+a0.y+a0.z+a0.w + a1.x+a1.y+a1.z+a1.w;
  s += __shfl_xor_sync(0xffffffffu, s, 1);
  s += __shfl_xor_sync(0xffffffffu, s, 2);
  s += __shfl_xor_sync(0xffffffffu, s, 4);
  float mean = s * (1.0f/64.0f);
  float d0=a0.x-mean, d1=a0.y-mean, d2=a0.z-mean, d3=a0.w-mean;
  float d4=a1.x-mean, d5=a1.y-mean, d6=a1.z-mean, d7=a1.w-mean;
  float sq = d0*d0+d1*d1+d2*d2+d3*d3+d4*d4+d5*d5+d6*d6+d7*d7;
  sq += __shfl_xor_sync(0xffffffffu, sq, 1);
  sq += __shfl_xor_sync(0xffffffffu, sq, 2);
  sq += __shfl_xor_sync(0xffffffffu, sq, 4);
  float inv = rsqrtf(sq*(1.0f/64.0f) + 1e-5f);
  float4 g0 = ((const float4*)(g + q*8))[0], g1 = ((const float4*)(g + q*8))[1];
  float4 b0 = ((const float4*)(b + q*8))[0], b1 = ((const float4*)(b + q*8))[1];
  float4 o0, o1;
  o0.x=d0*inv*g0.x+b0.x; o0.y=d1*inv*g0.y+b0.y; o0.z=d2*inv*g0.z+b0.z; o0.w=d3*inv*g0.w+b0.w;
  o1.x=d4*inv*g1.x+b1.x; o1.y=d5*inv*g1.y+b1.y; o1.z=d6*inv*g1.z+b1.z; o1.w=d7*inv*g1.w+b1.w;
  xp[0]=o0; xp[1]=o1;
}

// ---------------- fused LN1 + qk/v GEMM (scalar body, 32-row tiles, head-split) --------
__global__ __launch_bounds__(256) void k_lnqkv(const float* __restrict__ X,
                           const float* __restrict__ lg, const float* __restrict__ lb,
                           const float* __restrict__ Wq,
                           const float* __restrict__ Wv, float* __restrict__ qk,
                           float* __restrict__ v){
  __shared__ float Xs[32][68];
  __shared__ float Wqs[4096];
  __shared__ float Wvs[4096];
  int tid = threadIdx.x;
  int row0 = blockIdx.x*32;
  int tx = tid & 15, ty = tid >> 4;
  for (int i=tid;i<512;i+=256){
    int r=i>>4, c=i&15;
    *(float4*)&Xs[r][4*c] = *(const float4*)(X + (size_t)(row0+r)*64 + 4*c);
  }
  for (int i=tid;i<4096;i+=256){ Wqs[i]=Wq[i]; Wvs[i]=Wv[i]; }
  __syncthreads();
  ln_tile32(Xs, tid, lg, lb);
  __syncthreads();
  float aq[2][4]={{0.f,0.f,0.f,0.f},{0.f,0.f,0.f,0.f}};
  float av[2][4]={{0.f,0.f,0.f,0.f},{0.f,0.f,0.f,0.f}};
  #pragma unroll 4
  for (int k=0;k<64;k++){
    float x0 = Xs[ty*2][k], x1 = Xs[ty*2+1][k];
    #pragma unroll
    for (int cc=0;cc<4;cc++){
      float wq = Wqs[k*64 + tx + cc*16];
      float wv = Wvs[k*64 + tx + cc*16];
      aq[0][cc] += x0*wq; aq[1][cc] += x1*wq;
      av[0][cc] += x0*wv; av[1][cc] += x1*wv;
    }
  }
  #pragma unroll
  for (int rr=0;rr<2;rr++){
    int m = row0 + ty*2 + rr;
    int b = m / LPAD, t = m % LPAD;
    #pragma unroll
    for (int cc=0;cc<4;cc++){
      size_t oidx = ((size_t)(b*NH+cc)*LPAD + t)*DH + tx;  // head cc, dim tx
      qk[oidx] = aq[rr][cc];
      v[oidx]  = av[rr][cc];
    }
  }
}

// ---------------- fused combine + output GEMM + residual (scalar body, 32-row) ---------
__global__ __launch_bounds__(256) void k_wo(const float* __restrict__ o,
                       const float* __restrict__ lse,
                       const float* __restrict__ W,
                       const float* __restrict__ bias, float* __restrict__ Y){
  __shared__ float Xs[32][68];
  __shared__ float Ws[4096];
  int tid = threadIdx.x;
  int row0 = blockIdx.x*32;
  int tx = tid & 15, ty = tid >> 4;
  for (int i=tid;i<4096;i+=256) Ws[i]=W[i];
  // combine hash rounds into Xs: thread -> (row r, 8 cols)
  { int r = tid & 31, u = tid >> 5;              // u in 0..7
    int head = u >> 1, c0 = head*16 + (u&1)*8;
    int m = row0 + r; int b = m / LPAD, t = m % LPAD;
    int bh = b*NH + head;
    float ls[NR];
    #pragma unroll
    for (int rr=0;rr<NR;rr++) ls[rr] = lse[(size_t)(bh*NR+rr)*LPAD + t];
    float mx = fmaxf(fmaxf(ls[0],ls[1]), fmaxf(ls[2],ls[3]));
    float w[NR], s=0.f;
    #pragma unroll
    for (int rr=0;rr<NR;rr++){ w[rr]=__expf(ls[rr]-mx); s+=w[rr]; }
    float invs = 1.f/s;
    #pragma unroll
    for (int rr=0;rr<NR;rr++) w[rr] *= invs;
    const float* ob = o + ((size_t)(bh*NR)*LPAD + t)*DH + (u&1)*8;
    #pragma unroll
    for (int i=0;i<2;i++){
      float4 a = make_float4(0.f,0.f,0.f,0.f);
      #pragma unroll
      for (int rr=0;rr<NR;rr++){
        float4 ov = *(const float4*)(ob + (size_t)rr*LPAD*DH + 4*i);
        a.x += w[rr]*ov.x; a.y += w[rr]*ov.y; a.z += w[rr]*ov.z; a.w += w[rr]*ov.w;
      }
      *(float4*)&Xs[r][c0 + 4*i] = a;
    } }
  __syncthreads();
  float acc[2][4]={{0.f,0.f,0.f,0.f},{0.f,0.f,0.f,0.f}};
  #pragma unroll 4
  for (int k=0;k<64;k++){
    float x0 = Xs[ty*2][k], x1 = Xs[ty*2+1][k];
    #pragma unroll
    for (int cc=0;cc<4;cc++){
      float w = Ws[k*64 + tx + cc*16];
      acc[0][cc] += x0*w; acc[1][cc] += x1*w;
    }
  }
  #pragma unroll
  for (int rr=0;rr<2;rr++){
    int m = row0 + ty*2 + rr;
    #pragma unroll
    for (int cc=0;cc<4;cc++){
      int c = tx + cc*16;
      Y[(size_t)m*64 + c] += acc[rr][cc] + bias[c];
    }
  }
}

// ---------------- generic GEMM (scalar body, 32-row tiles) -------------------
// MODE 0: Y += val; MODE 1: Y = gelu(val). DOLN: layernorm X tile (requires K==64).
template<int N, int K, int MODE, int DOLN>
__global__ __launch_bounds__(256) void k_gemm(const float* __restrict__ X,
                       const float* __restrict__ W, const float* __restrict__ bias,
                       const float* __restrict__ lg, const float* __restrict__ lb,
                       float* __restrict__ Y){
  constexpr int KC = K/64, NC = N/64;
  __shared__ float Xs[32][68];
  __shared__ float Ws[4096];
  int tid = threadIdx.x;
  int tx = tid & 15, ty = tid >> 4;
  int row0 = blockIdx.x*32;
  float acc[NC][2][4];
  #pragma unroll
  for (int a=0;a<NC;a++)
    #pragma unroll
    for(int rr=0;rr<2;rr++)
      #pragma unroll
      for(int cc=0;cc<4;cc++) acc[a][rr][cc]=0.f;
  for (int kc=0;kc<KC;kc++){
    __syncthreads();
    for (int i=tid;i<512;i+=256){
      int r=i>>4, c=i&15;
      *(float4*)&Xs[r][4*c] = *(const float4*)(X + (size_t)(row0+r)*K + kc*64 + 4*c);
    }
    if (DOLN){
      __syncthreads();
      ln_tile32(Xs, tid, lg, lb);
    }
    for (int nc=0;nc<NC;nc++){
      __syncthreads();
      for (int i=tid;i<4096;i+=256){
        int k=i>>6, c=i&63;
        Ws[i]=W[(size_t)(kc*64+k)*N + nc*64 + c];
      }
      __syncthreads();
      #pragma unroll 4
      for (int k=0;k<64;k++){
        float x0=Xs[ty*2][k], x1=Xs[ty*2+1][k];
        #pragma unroll
        for (int cc=0;cc<4;cc++){
          float w=Ws[k*64 + tx + cc*16];
          acc[nc][0][cc]+=x0*w; acc[nc][1][cc]+=x1*w;
        }
      }
    }
  }
  #pragma unroll
  for (int nc=0;nc<NC;nc++){
    #pragma unroll
    for (int rr=0;rr<2;rr++){
      int m = row0 + ty*2 + rr;
      #pragma unroll
      for (int cc=0;cc<4;cc++){
        int c = nc*64 + tx + cc*16;
        float val = acc[nc][rr][cc] + bias[c];
        if (MODE==0) Y[(size_t)m*N + c] += val;
        else         Y[(size_t)m*N + c] = gelu_f(val);
      }
    }
  }
}

// ---------------- LSH hashing + per-segment histogram (fused, proven) ----------------
__global__ void k_hashcount(const float* __restrict__ qk, const float* __restrict__ rot,
                            unsigned char* __restrict__ bkt, int* __restrict__ cnt){
  __shared__ float rs[640];                      // rot (16,4,10)
  __shared__ int c[NR][NB];
  int tid = threadIdx.x;                         // 160
  int seg = blockIdx.x, bh = blockIdx.y;
  for (int i=tid;i<640;i+=160) rs[i]=rot[i];
  if (tid < NR*NB) ((int*)c)[tid] = 0;
  __syncthreads();
  int t = seg*160 + tid;
  const float4* qr = reinterpret_cast<const float4*>(qk + ((size_t)bh*LPAD + t)*DH);
  float q[16];
  #pragma unroll
  for (int i=0;i<4;i++){ float4 f4=qr[i]; q[4*i]=f4.x; q[4*i+1]=f4.y; q[4*i+2]=f4.z; q[4*i+3]=f4.w; }
  #pragma unroll
  for (int r=0;r<NR;r++){
    float p[10];
    #pragma unroll
    for (int i=0;i<10;i++){
      float s=0.f;
      #pragma unroll
      for (int f=0;f<16;f++) s += q[f]*rs[f*40 + r*10 + i];
      p[i]=s;
    }
    float best=-3.402823e38f; int bi=0;
    #pragma unroll
    for (int idx=0; idx<20; idx++){
      float val = (idx<10)? p[idx] : -p[idx-10];
      if (val>best){best=val;bi=idx;}           // first-max tie-break like jnp.argmax
    }
    bkt[((size_t)bh*NR + r)*LPAD + t] = (unsigned char)bi;
    atomicAdd(&c[r][bi], 1);
  }
  __syncthreads();
  if (tid < NR*NB){
    int r = tid / NB, b = tid % NB;
    cnt[((size_t)((bh*NR+r)*8 + seg))*NB + b] = c[r][b];
  }
}

// ---------------- fused prefix scan + stable scatter (uchar4 loads) ----------------
__global__ __launch_bounds__(640) void k_psort(const int* __restrict__ cnt,
                         const unsigned char* __restrict__ bkt,
                         short* __restrict__ sj){
  __shared__ int ws[20];
  __shared__ int offs[32][NB];                   // [(r,seg)][b]
  int bh = blockIdx.x;
  int i = threadIdx.x;                           // 640
  int r = i/160, b = (i%160)/8, seg = i%8;       // scan order (r,b,seg)
  int idx = ((bh*NR + r)*8 + seg)*NB + b;
  int v = cnt[idx];
  int lane = i & 31, w = i >> 5;
  int s = v;
  #pragma unroll
  for (int o=1;o<32;o<<=1){ int t=__shfl_up_sync(0xffffffffu, s, o); if (lane>=o) s+=t; }
  if (lane==31) ws[w]=s;
  __syncthreads();
  if (i < 32){
    int t = (i<20)? ws[i] : 0;
    #pragma unroll
    for (int o=1;o<32;o<<=1){ int u=__shfl_up_sync(0xffffffffu, t, o); if (i>=o) t+=u; }
    if (i<20) ws[i]=t;
  }
  __syncthreads();
  int base = (w>0)? ws[w-1] : 0;
  offs[r*8+seg][b] = base + s - v;
  __syncthreads();
  if (i < 32){
    int r2 = i >> 3, s2 = i & 7;
    const uchar4* p4 = (const uchar4*)(bkt + ((size_t)bh*NR + r2)*LPAD + s2*160);
    short* sjb = sj + (size_t)bh*NR*LPAD;
    int basej = r2*LPAD + s2*160;
    int* cc = offs[i];
    #pragma unroll 2
    for (int k=0;k<40;k++){
      uchar4 u = p4[k];
      int s3;
      s3 = cc[u.x]++; sjb[s3] = (short)(basej + 4*k);
      s3 = cc[u.y]++; sjb[s3] = (short)(basej + 4*k + 1);
      s3 = cc[u.z]++; sjb[s3] = (short)(basej + 4*k + 2);
      s3 = cc[u.w]++; sjb[s3] = (short)(basej + 4*k + 3);
    }
  }
}

// ---------------- chunked LSH attention, flash softmax, split-K x2 (proven R8) ---------
__global__ __launch_bounds__(128) void k_attn(const float* __restrict__ qk,
                       const float* __restrict__ v,
                       const short* __restrict__ sj, float* __restrict__ o,
                       float* __restrict__ lse){
  __shared__ float Ks[128][16];
  __shared__ float Vs[128][16];
  __shared__ int   tks[128];
  __shared__ float Pm[64], Pl[64];
  __shared__ float Pacc[64][16];
  int c = blockIdx.x, bh = blockIdx.y, tid = threadIdx.x;  // 128 threads
  int qi = tid & 63, half = tid >> 6;
  const short* sjb = sj + (size_t)bh*NR*LPAD;
  int jq = sjb[c*BSZ + qi];
  int tq = jq % LPAD, rq = jq / LPAD;
  ull qv[8];
  { const ulonglong2* qr = reinterpret_cast<const ulonglong2*>(qk + ((size_t)bh*LPAD + tq)*DH);
    #pragma unroll
    for (int i=0;i<4;i++){ ulonglong2 u=qr[i]; qv[2*i]=u.x; qv[2*i+1]=u.y; } }
  int prev = (c + NCH - 1) % NCH;
  { int kk = tid;
    int cc = (kk<64)? c : prev;
    int jk = sjb[cc*BSZ + (kk&63)];
    int tk = jk % LPAD;
    float kvv[16];
    { const float4* kr = reinterpret_cast<const float4*>(qk + ((size_t)bh*LPAD + tk)*DH);
      #pragma unroll
      for (int i=0;i<4;i++){ float4 f4=kr[i]; kvv[4*i]=f4.x; kvv[4*i+1]=f4.y; kvv[4*i+2]=f4.z; kvv[4*i+3]=f4.w; } }
    float ss=0.f;
    #pragma unroll
    for (int f=0;f<16;f++) ss += kvv[f]*kvv[f];
    float inv = 1.0f / fmaxf(sqrtf(ss), 1e-12f);
    float4* kd = (float4*)&Ks[kk][0];
    #pragma unroll
    for (int i=0;i<4;i++){
      float4 f4; f4.x=kvv[4*i]*inv; f4.y=kvv[4*i+1]*inv; f4.z=kvv[4*i+2]*inv; f4.w=kvv[4*i+3]*inv;
      kd[i]=f4;
    }
    { const float4* vr = reinterpret_cast<const float4*>(v + ((size_t)bh*LPAD + tk)*DH);
      float4* vd = (float4*)&Vs[kk][0];
      #pragma unroll
      for (int i=0;i<4;i++) vd[i]=vr[i];
    }
    tks[kk]=tk;
  }
  __syncthreads();
  float m=-3.0e38f, l=0.f;
  ull acc2[8];
  #pragma unroll
  for (int f=0;f<8;f++) acc2[f]=0ull;
  int jbase = half << 6;
  #pragma unroll 2
  for (int jj=0;jj<64;jj++){
    int j = jbase + jj;
    const ulonglong2* kr = (const ulonglong2*)&Ks[j][0];
    ull d2 = 0ull;
    #pragma unroll
    for (int i=0;i<4;i++){
      ulonglong2 u = kr[i];
      fma2(d2, qv[2*i],   u.x);
      fma2(d2, qv[2*i+1], u.y);
    }
    float d = hsum2(d2) * 0.25f;                 // DH^-0.5
    if (tks[j]==tq) d = -50000.0f;               // SELF_ATTN_VAL
    if (d>m){
      float sc=__expf(m-d);
      l*=sc;
      ull sc2 = pack2(sc,sc);
      #pragma unroll
      for (int f=0;f<8;f++) mul2(acc2[f], acc2[f], sc2);
      m=d;
    }
    float p=__expf(d-m);
    l += p;
    ull p2 = pack2(p,p);
    const ulonglong2* vr = (const ulonglong2*)&Vs[j][0];
    #pragma unroll
    for (int i=0;i<4;i++){
      ulonglong2 u = vr[i];
      fma2(acc2[2*i],   p2, u.x);
      fma2(acc2[2*i+1], p2, u.y);
    }
  }
  if (half){
    Pm[qi]=m; Pl[qi]=l;
    float tmp[16];
    #pragma unroll
    for (int f=0;f<8;f++) unpack2(acc2[f], tmp[2*f], tmp[2*f+1]);
    float4* pa = (float4*)Pacc[qi];
    #pragma unroll
    for (int i=0;i<4;i++){
      float4 f4; f4.x=tmp[4*i]; f4.y=tmp[4*i+1]; f4.z=tmp[4*i+2]; f4.w=tmp[4*i+3];
      pa[i]=f4;
    }
  }
  __syncthreads();
  if (!half){
    float m2 = Pm[qi], l2 = Pl[qi];
    float M = fmaxf(m, m2);
    float s1 = __expf(m - M), s2 = __expf(m2 - M);
    float L = l*s1 + l2*s2;
    float invl = 1.0f/L;
    float out[16];
    #pragma unroll
    for (int f=0;f<8;f++) unpack2(acc2[f], out[2*f], out[2*f+1]);
    const float4* pa = (const float4*)Pacc[qi];
    float4* op = (float4*)(o + ((size_t)(bh*NR + rq)*LPAD + tq)*DH);  // scatter == undo_sort
    #pragma unroll
    for (int i=0;i<4;i++){
      float4 p = pa[i];
      float4 f4;
      f4.x = (out[4*i+0]*s1 + p.x*s2)*invl;
      f4.y = (out[4*i+1]*s1 + p.y*s2)*invl;
      f4.z = (out[4*i+2]*s1 + p.z*s2)*invl;
      f4.w = (out[4*i+3]*s1 + p.w*s2)*invl;
      op[i]=f4;
    }
    lse[(size_t)(bh*NR+rq)*LPAD + tq] = M + logf(L);
  }
}

// ---------------- final: y = ((x1+x2)*0.5) @ out_w + out_b, trim to 1250 ----------------
__global__ void k_final(const float* __restrict__ x1, const float* __restrict__ x2,
                        const float* __restrict__ ow, const float* __restrict__ ob,
                        float* __restrict__ y){
  int row  = blockIdx.x*4 + (threadIdx.x>>5);    // 16*1250 rows
  int lane = threadIdx.x & 31;
  int b = row / LIN, t = row % LIN;
  size_t base = ((size_t)b*LPAD + t)*DM;
  float s = (x1[base+lane]+x2[base+lane])*0.5f*ow[lane]
          + (x1[base+lane+32]+x2[base+lane+32])*0.5f*ow[lane+32];
  #pragma unroll
  for (int o2=16;o2>0;o2>>=1) s += __shfl_xor_sync(0xffffffffu, s, o2);
  if (lane==0) y[row] = s + ob[0];
}

// ---------------- host launcher ----------------
extern "C" void kernel_launch(void* const* d_in, const int* in_sizes, int n_in,
                              void* d_out, int out_size){
  const float* wave  = (const float*)d_in[0];
  const float* in_w  = (const float*)d_in[1];
  const float* in_b  = (const float*)d_in[2];
  const float* ln1_g = (const float*)d_in[3];
  const float* ln1_b = (const float*)d_in[4];
  const float* wqk   = (const float*)d_in[5];
  const float* wv    = (const float*)d_in[6];
  const float* wo_w  = (const float*)d_in[7];
  const float* wo_b  = (const float*)d_in[8];
  const float* rot   = (const float*)d_in[9];
  const float* ln2_g = (const float*)d_in[10];
  const float* ln2_b = (const float*)d_in[11];
  const float* w1    = (const float*)d_in[12];
  const float* b1    = (const float*)d_in[13];
  const float* w2    = (const float*)d_in[14];
  const float* b2    = (const float*)d_in[15];
  const float* out_w = (const float*)d_in[16];
  const float* out_b = (const float*)d_in[17];

  float *x1,*x2,*qkp,*vp,*op,*lsp,*ffp;
  unsigned char* bktp; int *cntp; short* sjp;
  cudaGetSymbolAddress((void**)&x1,  g_x1);
  cudaGetSymbolAddress((void**)&x2,  g_x2);
  cudaGetSymbolAddress((void**)&qkp, g_qk);
  cudaGetSymbolAddress((void**)&vp,  g_v);
  cudaGetSymbolAddress((void**)&bktp,g_bkt);
  cudaGetSymbolAddress((void**)&cntp,g_cnt);
  cudaGetSymbolAddress((void**)&sjp, g_sj);
  cudaGetSymbolAddress((void**)&op,  g_o);
  cudaGetSymbolAddress((void**)&lsp, g_lse);
  cudaGetSymbolAddress((void**)&ffp, g_ffh);

  k_embed<<<5120,256>>>(wave, in_w, in_b, x1, x2);

  for (int i=0;i<4;i++){
    k_lnqkv<<<640,256>>>(x2, ln1_g+i*64, ln1_b+i*64, wqk+i*4096, wv+i*4096, qkp, vp);
    k_hashcount<<<dim3(8,64),160>>>(qkp, rot+i*640, bktp, cntp);
    k_psort<<<64,640>>>(cntp, bktp, sjp);
    k_attn<<<dim3(80,64),128>>>(qkp, vp, sjp, op, lsp);
    k_wo<<<640,256>>>(op, lsp, wo_w+i*4096, wo_b+i*64, x1);
    k_gemm<256,64,1,1><<<640,256>>>(x1, w1+i*16384, b1+i*256,
                                    ln2_g+i*64, ln2_b+i*64, ffp);
    k_gemm<64,256,0,0><<<640,256>>>(ffp, w2+i*16384, b2+i*64,
                                    (const float*)0, (const float*)0, x2);
  }

  k_final<<<5000,128>>>(x1, x2, out_w, out_b, (float*)d_out);
}

// round 15
// speedup vs baseline: 1.2845x; 1.0427x over previous
#include <cuda_runtime.h>
#include <math.h>

#define NBATCH 16
#define LPAD 1280
#define LIN 1250
#define DM 64
#define NH 4
#define DH 16
#define NR 4        // hash rounds
#define BSZ 64      // bucket chunk size
#define NB 20       // buckets per round
#define NCH 80      // NR*NB chunks
#define BHH 64      // NBATCH*NH
#define MR 20480    // NBATCH*LPAD
#define FF 256

typedef unsigned long long ull;

__device__ __forceinline__ ull pack2(float lo, float hi){
  ull r; asm("mov.b64 %0,{%1,%2};" : "=l"(r) : "f"(lo), "f"(hi)); return r;
}
__device__ __forceinline__ void unpack2(ull a, float& lo, float& hi){
  asm("mov.b64 {%0,%1},%2;" : "=f"(lo), "=f"(hi) : "l"(a));
}
__device__ __forceinline__ void fma2(ull& d, ull a, ull b){
  asm("fma.rn.f32x2 %0,%1,%2,%0;" : "+l"(d) : "l"(a), "l"(b));
}
__device__ __forceinline__ void mul2(ull& d, ull a, ull b){
  asm("mul.rn.f32x2 %0,%1,%2;" : "=l"(d) : "l"(a), "l"(b));
}
__device__ __forceinline__ float hsum2(ull a){
  float lo, hi; unpack2(a, lo, hi); return lo + hi;
}

// ---------------- scratch (device globals; no allocation allowed) ----------------
__device__ float g_x1[MR*DM];
__device__ float g_x2[MR*DM];
__device__ float g_qk[BHH*LPAD*DH];
__device__ float g_v [BHH*LPAD*DH];
__device__ unsigned char g_bkt[BHH*NR*LPAD];
__device__ int   g_cnt[BHH*NR*8*NB];
__device__ short g_sj [BHH*NR*LPAD];
__device__ float g_o  [BHH*NR*LPAD*DH];
__device__ float g_lse[BHH*NR*LPAD];
__device__ float g_ffh[MR*FF];

// ---------------- embed: x = pad(wave^T) @ in_w + in_b ----------------
__global__ void k_embed(const float* __restrict__ wave, const float* __restrict__ in_w,
                        const float* __restrict__ in_b, float* __restrict__ x1,
                        float* __restrict__ x2){
  int gid = blockIdx.x*256 + threadIdx.x;       // 16*1280*64 total
  int d = gid & 63;
  int t = (gid >> 6) % LPAD;
  int b = gid / (LPAD*64);
  float val = in_b[d];
  if (t < LIN)
    val += wave[b*2*LIN + t]*in_w[d] + wave[b*2*LIN + LIN + t]*in_w[64+d];
  x1[gid] = val; x2[gid] = val;
}

__device__ __forceinline__ float gelu_f(float x){
  return 0.5f*x*(1.0f + erff(x*0.7071067811865476f));
}

// In-shared-tile layernorm, 32-row tile [68] stride: 8 threads/row, 8 cols each.
__device__ __forceinline__ void ln_tile32(float (*Xs)[68], int tid,
                                          const float* __restrict__ g,
                                          const float* __restrict__ b){
  int r = tid >> 3, q = tid & 7;
  float4* xp = (float4*)&Xs[r][q*8];
  float4 a0 = xp[0], a1 = xp[1];
  float s = a0.x+a0.y+a0.z+a0.w + a1.x+a1.y+a1.z+a1.w;
  s += __shfl_xor_sync(0xffffffffu, s, 1);
  s += __shfl_xor_sync(0xffffffffu, s, 2);
  s += __shfl_xor_sync(0xffffffffu, s, 4);
  float mean = s * (1.0f/64.0f);
  float d0=a0.x-mean, d1=a0.y-mean, d2=a0.z-mean, d3=a0.w-mean;
  float d4=a1.x-mean, d5=a1.y-mean, d6=a1.z-mean, d7=a1.w-mean;
  float sq = d0*d0+d1*d1+d2*d2+d3*d3+d4*d4+d5*d5+d6*d6+d7*d7;
  sq += __shfl_xor_sync(0xffffffffu, sq, 1);
  sq += __shfl_xor_sync(0xffffffffu, sq, 2);
  sq += __shfl_xor_sync(0xffffffffu, sq, 4);
  float inv = rsqrtf(sq*(1.0f/64.0f) + 1e-5f);
  float4 g0 = ((const float4*)(g + q*8))[0], g1 = ((const float4*)(g + q*8))[1];
  float4 b0 = ((const float4*)(b + q*8))[0], b1 = ((const float4*)(b + q*8))[1];
  float4 o0, o1;
  o0.x=d0*inv*g0.x+b0.x; o0.y=d1*inv*g0.y+b0.y; o0.z=d2*inv*g0.z+b0.z; o0.w=d3*inv*g0.w+b0.w;
  o1.x=d4*inv*g1.x+b1.x; o1.y=d5*inv*g1.y+b1.y; o1.z=d6*inv*g1.z+b1.z; o1.w=d7*inv*g1.w+b1.w;
  xp[0]=o0; xp[1]=o1;
}

// ---------------- fused LN1 + qk/v GEMM (f32x2 pair-column, flat Ws, head-split) --------
__global__ __launch_bounds__(256) void k_lnqkv(const float* __restrict__ X,
                           const float* __restrict__ lg, const float* __restrict__ lb,
                           const float* __restrict__ Wq,
                           const float* __restrict__ Wv, float* __restrict__ qk,
                           float* __restrict__ v){
  __shared__ float Xs[32][68];
  __shared__ float Wqs[4096];
  __shared__ float Wvs[4096];
  int tid = threadIdx.x;
  int row0 = blockIdx.x*32;
  int tx = tid & 15, ty = tid >> 4;
  for (int i=tid;i<512;i+=256){
    int r=i>>4, c=i&15;
    *(float4*)&Xs[r][4*c] = *(const float4*)(X + (size_t)(row0+r)*64 + 4*c);
  }
  for (int i=tid;i<4096;i+=256){ Wqs[i]=Wq[i]; Wvs[i]=Wv[i]; }
  __syncthreads();
  ln_tile32(Xs, tid, lg, lb);
  __syncthreads();
  ull aq[2][2]={{0ull,0ull},{0ull,0ull}};
  ull av[2][2]={{0ull,0ull},{0ull,0ull}};
  #pragma unroll 4
  for (int k=0;k<64;k++){
    float x0 = Xs[ty*2][k], x1 = Xs[ty*2+1][k];
    ull xx0 = pack2(x0,x0), xx1 = pack2(x1,x1);
    #pragma unroll
    for (int cc=0;cc<2;cc++){
      ull wq = *(const ull*)&Wqs[k*64 + 2*tx + 32*cc];
      ull wv = *(const ull*)&Wvs[k*64 + 2*tx + 32*cc];
      fma2(aq[0][cc], xx0, wq); fma2(aq[1][cc], xx1, wq);
      fma2(av[0][cc], xx0, wv); fma2(av[1][cc], xx1, wv);
    }
  }
  #pragma unroll
  for (int rr=0;rr<2;rr++){
    int m = row0 + ty*2 + rr;
    int b = m / LPAD, t = m % LPAD;
    #pragma unroll
    for (int cc=0;cc<2;cc++){
      int c = 2*tx + 32*cc;                      // output column 0..63
      int head = c >> 4, d0 = c & 15;            // pair stays within one head (c even)
      size_t base = ((size_t)(b*NH+head)*LPAD + t)*DH + d0;
      float lo, hi;
      unpack2(aq[rr][cc], lo, hi);
      *(float2*)(qk + base) = make_float2(lo, hi);
      unpack2(av[rr][cc], lo, hi);
      *(float2*)(v + base) = make_float2(lo, hi);
    }
  }
}

// ---------------- fused combine + output GEMM + residual (f32x2 pair-column) ------------
__global__ __launch_bounds__(256) void k_wo(const float* __restrict__ o,
                       const float* __restrict__ lse,
                       const float* __restrict__ W,
                       const float* __restrict__ bias, float* __restrict__ Y){
  __shared__ float Xs[32][68];
  __shared__ float Ws[4096];
  int tid = threadIdx.x;
  int row0 = blockIdx.x*32;
  int tx = tid & 15, ty = tid >> 4;
  for (int i=tid;i<4096;i+=256) Ws[i]=W[i];
  // combine hash rounds into Xs: thread -> (row r, 8 cols)
  { int r = tid & 31, u = tid >> 5;              // u in 0..7
    int head = u >> 1, c0 = head*16 + (u&1)*8;
    int m = row0 + r; int b = m / LPAD, t = m % LPAD;
    int bh = b*NH + head;
    float ls[NR];
    #pragma unroll
    for (int rr=0;rr<NR;rr++) ls[rr] = lse[(size_t)(bh*NR+rr)*LPAD + t];
    float mx = fmaxf(fmaxf(ls[0],ls[1]), fmaxf(ls[2],ls[3]));
    float w[NR], s=0.f;
    #pragma unroll
    for (int rr=0;rr<NR;rr++){ w[rr]=__expf(ls[rr]-mx); s+=w[rr]; }
    float invs = 1.f/s;
    #pragma unroll
    for (int rr=0;rr<NR;rr++) w[rr] *= invs;
    const float* ob = o + ((size_t)(bh*NR)*LPAD + t)*DH + (u&1)*8;
    #pragma unroll
    for (int i=0;i<2;i++){
      float4 a = make_float4(0.f,0.f,0.f,0.f);
      #pragma unroll
      for (int rr=0;rr<NR;rr++){
        float4 ov = *(const float4*)(ob + (size_t)rr*LPAD*DH + 4*i);
        a.x += w[rr]*ov.x; a.y += w[rr]*ov.y; a.z += w[rr]*ov.z; a.w += w[rr]*ov.w;
      }
      *(float4*)&Xs[r][c0 + 4*i] = a;
    } }
  __syncthreads();
  ull acc[2][2]={{0ull,0ull},{0ull,0ull}};
  #pragma unroll 4
  for (int k=0;k<64;k++){
    float x0 = Xs[ty*2][k], x1 = Xs[ty*2+1][k];
    ull xx0 = pack2(x0,x0), xx1 = pack2(x1,x1);
    #pragma unroll
    for (int cc=0;cc<2;cc++){
      ull w = *(const ull*)&Ws[k*64 + 2*tx + 32*cc];
      fma2(acc[0][cc], xx0, w);
      fma2(acc[1][cc], xx1, w);
    }
  }
  #pragma unroll
  for (int rr=0;rr<2;rr++){
    int m = row0 + ty*2 + rr;
    #pragma unroll
    for (int cc=0;cc<2;cc++){
      int c = 2*tx + 32*cc;
      float lo, hi;
      unpack2(acc[rr][cc], lo, hi);
      float2* yp = (float2*)(Y + (size_t)m*64 + c);
      float2 prev = *yp;
      *yp = make_float2(prev.x + lo + bias[c], prev.y + hi + bias[c+1]);
    }
  }
}

// ---------------- generic GEMM (f32x2 pair-column, flat Ws, 32-row tiles) --------------
// MODE 0: Y += val; MODE 1: Y = gelu(val). DOLN: layernorm X tile (requires K==64).
template<int N, int K, int MODE, int DOLN>
__global__ __launch_bounds__(256) void k_gemm(const float* __restrict__ X,
                       const float* __restrict__ W, const float* __restrict__ bias,
                       const float* __restrict__ lg, const float* __restrict__ lb,
                       float* __restrict__ Y){
  constexpr int KC = K/64, NC = N/64;
  __shared__ float Xs[32][68];
  __shared__ float Ws[4096];
  int tid = threadIdx.x;
  int tx = tid & 15, ty = tid >> 4;
  int row0 = blockIdx.x*32;
  ull acc[NC][2][2];
  #pragma unroll
  for (int a=0;a<NC;a++)
    #pragma unroll
    for(int rr=0;rr<2;rr++)
      #pragma unroll
      for(int cc=0;cc<2;cc++) acc[a][rr][cc]=0ull;
  for (int kc=0;kc<KC;kc++){
    __syncthreads();
    for (int i=tid;i<512;i+=256){
      int r=i>>4, c=i&15;
      *(float4*)&Xs[r][4*c] = *(const float4*)(X + (size_t)(row0+r)*K + kc*64 + 4*c);
    }
    if (DOLN){
      __syncthreads();
      ln_tile32(Xs, tid, lg, lb);
    }
    for (int nc=0;nc<NC;nc++){
      __syncthreads();
      for (int i=tid;i<4096;i+=256){
        int k=i>>6, c=i&63;
        Ws[i]=W[(size_t)(kc*64+k)*N + nc*64 + c];
      }
      __syncthreads();
      #pragma unroll 4
      for (int k=0;k<64;k++){
        float x0=Xs[ty*2][k], x1=Xs[ty*2+1][k];
        ull xx0 = pack2(x0,x0), xx1 = pack2(x1,x1);
        #pragma unroll
        for (int cc=0;cc<2;cc++){
          ull w = *(const ull*)&Ws[k*64 + 2*tx + 32*cc];
          fma2(acc[nc][0][cc], xx0, w);
          fma2(acc[nc][1][cc], xx1, w);
        }
      }
    }
  }
  #pragma unroll
  for (int nc=0;nc<NC;nc++){
    #pragma unroll
    for (int rr=0;rr<2;rr++){
      int m = row0 + ty*2 + rr;
      #pragma unroll
      for (int cc=0;cc<2;cc++){
        int c = nc*64 + 2*tx + 32*cc;
        float lo, hi;
        unpack2(acc[nc][rr][cc], lo, hi);
        float v0 = lo + bias[c], v1 = hi + bias[c+1];
        float2* yp = (float2*)(Y + (size_t)m*N + c);
        if (MODE==0){
          float2 prev = *yp;
          *yp = make_float2(prev.x + v0, prev.y + v1);
        } else {
          *yp = make_float2(gelu_f(v0), gelu_f(v1));
        }
      }
    }
  }
}

// ---------------- LSH hashing + per-segment histogram (fused, proven) ----------------
__global__ void k_hashcount(const float* __restrict__ qk, const float* __restrict__ rot,
                            unsigned char* __restrict__ bkt, int* __restrict__ cnt){
  __shared__ float rs[640];                      // rot (16,4,10)
  __shared__ int c[NR][NB];
  int tid = threadIdx.x;                         // 160
  int seg = blockIdx.x, bh = blockIdx.y;
  for (int i=tid;i<640;i+=160) rs[i]=rot[i];
  if (tid < NR*NB) ((int*)c)[tid] = 0;
  __syncthreads();
  int t = seg*160 + tid;
  const float4* qr = reinterpret_cast<const float4*>(qk + ((size_t)bh*LPAD + t)*DH);
  float q[16];
  #pragma unroll
  for (int i=0;i<4;i++){ float4 f4=qr[i]; q[4*i]=f4.x; q[4*i+1]=f4.y; q[4*i+2]=f4.z; q[4*i+3]=f4.w; }
  #pragma unroll
  for (int r=0;r<NR;r++){
    float p[10];
    #pragma unroll
    for (int i=0;i<10;i++){
      float s=0.f;
      #pragma unroll
      for (int f=0;f<16;f++) s += q[f]*rs[f*40 + r*10 + i];
      p[i]=s;
    }
    float best=-3.402823e38f; int bi=0;
    #pragma unroll
    for (int idx=0; idx<20; idx++){
      float val = (idx<10)? p[idx] : -p[idx-10];
      if (val>best){best=val;bi=idx;}           // first-max tie-break like jnp.argmax
    }
    bkt[((size_t)bh*NR + r)*LPAD + t] = (unsigned char)bi;
    atomicAdd(&c[r][bi], 1);
  }
  __syncthreads();
  if (tid < NR*NB){
    int r = tid / NB, b = tid % NB;
    cnt[((size_t)((bh*NR+r)*8 + seg))*NB + b] = c[r][b];
  }
}

// ---------------- fused prefix scan + stable scatter (uchar4 loads) ----------------
__global__ __launch_bounds__(640) void k_psort(const int* __restrict__ cnt,
                         const unsigned char* __restrict__ bkt,
                         short* __restrict__ sj){
  __shared__ int ws[20];
  __shared__ int offs[32][NB];                   // [(r,seg)][b]
  int bh = blockIdx.x;
  int i = threadIdx.x;                           // 640
  int r = i/160, b = (i%160)/8, seg = i%8;       // scan order (r,b,seg)
  int idx = ((bh*NR + r)*8 + seg)*NB + b;
  int v = cnt[idx];
  int lane = i & 31, w = i >> 5;
  int s = v;
  #pragma unroll
  for (int o=1;o<32;o<<=1){ int t=__shfl_up_sync(0xffffffffu, s, o); if (lane>=o) s+=t; }
  if (lane==31) ws[w]=s;
  __syncthreads();
  if (i < 32){
    int t = (i<20)? ws[i] : 0;
    #pragma unroll
    for (int o=1;o<32;o<<=1){ int u=__shfl_up_sync(0xffffffffu, t, o); if (i>=o) t+=u; }
    if (i<20) ws[i]=t;
  }
  __syncthreads();
  int base = (w>0)? ws[w-1] : 0;
  offs[r*8+seg][b] = base + s - v;
  __syncthreads();
  if (i < 32){
    int r2 = i >> 3, s2 = i & 7;
    const uchar4* p4 = (const uchar4*)(bkt + ((size_t)bh*NR + r2)*LPAD + s2*160);
    short* sjb = sj + (size_t)bh*NR*LPAD;
    int basej = r2*LPAD + s2*160;
    int* cc = offs[i];
    #pragma unroll 2
    for (int k=0;k<40;k++){
      uchar4 u = p4[k];
      int s3;
      s3 = cc[u.x]++; sjb[s3] = (short)(basej + 4*k);
      s3 = cc[u.y]++; sjb[s3] = (short)(basej + 4*k + 1);
      s3 = cc[u.z]++; sjb[s3] = (short)(basej + 4*k + 2);
      s3 = cc[u.w]++; sjb[s3] = (short)(basej + 4*k + 3);
    }
  }
}

// ---------------- chunked LSH attention, flash softmax, split-K x2 (proven R8) ---------
__global__ __launch_bounds__(128) void k_attn(const float* __restrict__ qk,
                       const float* __restrict__ v,
                       const short* __restrict__ sj, float* __restrict__ o,
                       float* __restrict__ lse){
  __shared__ float Ks[128][16];
  __shared__ float Vs[128][16];
  __shared__ int   tks[128];
  __shared__ float Pm[64], Pl[64];
  __shared__ float Pacc[64][16];
  int c = blockIdx.x, bh = blockIdx.y, tid = threadIdx.x;  // 128 threads
  int qi = tid & 63, half = tid >> 6;
  const short* sjb = sj + (size_t)bh*NR*LPAD;
  int jq = sjb[c*BSZ + qi];
  int tq = jq % LPAD, rq = jq / LPAD;
  ull qv[8];
  { const ulonglong2* qr = reinterpret_cast<const ulonglong2*>(qk + ((size_t)bh*LPAD + tq)*DH);
    #pragma unroll
    for (int i=0;i<4;i++){ ulonglong2 u=qr[i]; qv[2*i]=u.x; qv[2*i+1]=u.y; } }
  int prev = (c + NCH - 1) % NCH;
  { int kk = tid;
    int cc = (kk<64)? c : prev;
    int jk = sjb[cc*BSZ + (kk&63)];
    int tk = jk % LPAD;
    float kvv[16];
    { const float4* kr = reinterpret_cast<const float4*>(qk + ((size_t)bh*LPAD + tk)*DH);
      #pragma unroll
      for (int i=0;i<4;i++){ float4 f4=kr[i]; kvv[4*i]=f4.x; kvv[4*i+1]=f4.y; kvv[4*i+2]=f4.z; kvv[4*i+3]=f4.w; } }
    float ss=0.f;
    #pragma unroll
    for (int f=0;f<16;f++) ss += kvv[f]*kvv[f];
    float inv = 1.0f / fmaxf(sqrtf(ss), 1e-12f);
    float4* kd = (float4*)&Ks[kk][0];
    #pragma unroll
    for (int i=0;i<4;i++){
      float4 f4; f4.x=kvv[4*i]*inv; f4.y=kvv[4*i+1]*inv; f4.z=kvv[4*i+2]*inv; f4.w=kvv[4*i+3]*inv;
      kd[i]=f4;
    }
    { const float4* vr = reinterpret_cast<const float4*>(v + ((size_t)bh*LPAD + tk)*DH);
      float4* vd = (float4*)&Vs[kk][0];
      #pragma unroll
      for (int i=0;i<4;i++) vd[i]=vr[i];
    }
    tks[kk]=tk;
  }
  __syncthreads();
  float m=-3.0e38f, l=0.f;
  ull acc2[8];
  #pragma unroll
  for (int f=0;f<8;f++) acc2[f]=0ull;
  int jbase = half << 6;
  #pragma unroll 2
  for (int jj=0;jj<64;jj++){
    int j = jbase + jj;
    const ulonglong2* kr = (const ulonglong2*)&Ks[j][0];
    ull d2 = 0ull;
    #pragma unroll
    for (int i=0;i<4;i++){
      ulonglong2 u = kr[i];
      fma2(d2, qv[2*i],   u.x);
      fma2(d2, qv[2*i+1], u.y);
    }
    float d = hsum2(d2) * 0.25f;                 // DH^-0.5
    if (tks[j]==tq) d = -50000.0f;               // SELF_ATTN_VAL
    if (d>m){
      float sc=__expf(m-d);
      l*=sc;
      ull sc2 = pack2(sc,sc);
      #pragma unroll
      for (int f=0;f<8;f++) mul2(acc2[f], acc2[f], sc2);
      m=d;
    }
    float p=__expf(d-m);
    l += p;
    ull p2 = pack2(p,p);
    const ulonglong2* vr = (const ulonglong2*)&Vs[j][0];
    #pragma unroll
    for (int i=0;i<4;i++){
      ulonglong2 u = vr[i];
      fma2(acc2[2*i],   p2, u.x);
      fma2(acc2[2*i+1], p2, u.y);
    }
  }
  if (half){
    Pm[qi]=m; Pl[qi]=l;
    float tmp[16];
    #pragma unroll
    for (int f=0;f<8;f++) unpack2(acc2[f], tmp[2*f], tmp[2*f+1]);
    float4* pa = (float4*)Pacc[qi];
    #pragma unroll
    for (int i=0;i<4;i++){
      float4 f4; f4.x=tmp[4*i]; f4.y=tmp[4*i+1]; f4.z=tmp[4*i+2]; f4.w=tmp[4*i+3];
      pa[i]=f4;
    }
  }
  __syncthreads();
  if (!half){
    float m2 = Pm[qi], l2 = Pl[qi];
    float M = fmaxf(m, m2);
    float s1 = __expf(m - M), s2 = __expf(m2 - M);
    float L = l*s1 + l2*s2;
    float invl = 1.0f/L;
    float out[16];
    #pragma unroll
    for (int f=0;f<8;f++) unpack2(acc2[f], out[2*f], out[2*f+1]);
    const float4* pa = (const float4*)Pacc[qi];
    float4* op = (float4*)(o + ((size_t)(bh*NR + rq)*LPAD + tq)*DH);  // scatter == undo_sort
    #pragma unroll
    for (int i=0;i<4;i++){
      float4 p = pa[i];
      float4 f4;
      f4.x = (out[4*i+0]*s1 + p.x*s2)*invl;
      f4.y = (out[4*i+1]*s1 + p.y*s2)*invl;
      f4.z = (out[4*i+2]*s1 + p.z*s2)*invl;
      f4.w = (out[4*i+3]*s1 + p.w*s2)*invl;
      op[i]=f4;
    }
    lse[(size_t)(bh*NR+rq)*LPAD + tq] = M + logf(L);
  }
}

// ---------------- final: y = ((x1+x2)*0.5) @ out_w + out_b, trim to 1250 ----------------
__global__ void k_final(const float* __restrict__ x1, const float* __restrict__ x2,
                        const float* __restrict__ ow, const float* __restrict__ ob,
                        float* __restrict__ y){
  int row  = blockIdx.x*4 + (threadIdx.x>>5);    // 16*1250 rows
  int lane = threadIdx.x & 31;
  int b = row / LIN, t = row % LIN;
  size_t base = ((size_t)b*LPAD + t)*DM;
  float s = (x1[base+lane]+x2[base+lane])*0.5f*ow[lane]
          + (x1[base+lane+32]+x2[base+lane+32])*0.5f*ow[lane+32];
  #pragma unroll
  for (int o2=16;o2>0;o2>>=1) s += __shfl_xor_sync(0xffffffffu, s, o2);
  if (lane==0) y[row] = s + ob[0];
}

// ---------------- host launcher ----------------
extern "C" void kernel_launch(void* const* d_in, const int* in_sizes, int n_in,
                              void* d_out, int out_size){
  const float* wave  = (const float*)d_in[0];
  const float* in_w  = (const float*)d_in[1];
  const float* in_b  = (const float*)d_in[2];
  const float* ln1_g = (const float*)d_in[3];
  const float* ln1_b = (const float*)d_in[4];
  const float* wqk   = (const float*)d_in[5];
  const float* wv    = (const float*)d_in[6];
  const float* wo_w  = (const float*)d_in[7];
  const float* wo_b  = (const float*)d_in[8];
  const float* rot   = (const float*)d_in[9];
  const float* ln2_g = (const float*)d_in[10];
  const float* ln2_b = (const float*)d_in[11];
  const float* w1    = (const float*)d_in[12];
  const float* b1    = (const float*)d_in[13];
  const float* w2    = (const float*)d_in[14];
  const float* b2    = (const float*)d_in[15];
  const float* out_w = (const float*)d_in[16];
  const float* out_b = (const float*)d_in[17];

  float *x1,*x2,*qkp,*vp,*op,*lsp,*ffp;
  unsigned char* bktp; int *cntp; short* sjp;
  cudaGetSymbolAddress((void**)&x1,  g_x1);
  cudaGetSymbolAddress((void**)&x2,  g_x2);
  cudaGetSymbolAddress((void**)&qkp, g_qk);
  cudaGetSymbolAddress((void**)&vp,  g_v);
  cudaGetSymbolAddress((void**)&bktp,g_bkt);
  cudaGetSymbolAddress((void**)&cntp,g_cnt);
  cudaGetSymbolAddress((void**)&sjp, g_sj);
  cudaGetSymbolAddress((void**)&op,  g_o);
  cudaGetSymbolAddress((void**)&lsp, g_lse);
  cudaGetSymbolAddress((void**)&ffp, g_ffh);

  k_embed<<<5120,256>>>(wave, in_w, in_b, x1, x2);

  for (int i=0;i<4;i++){
    k_lnqkv<<<640,256>>>(x2, ln1_g+i*64, ln1_b+i*64, wqk+i*4096, wv+i*4096, qkp, vp);
    k_hashcount<<<dim3(8,64),160>>>(qkp, rot+i*640, bktp, cntp);
    k_psort<<<64,640>>>(cntp, bktp, sjp);
    k_attn<<<dim3(80,64),128>>>(qkp, vp, sjp, op, lsp);
    k_wo<<<640,256>>>(op, lsp, wo_w+i*4096, wo_b+i*64, x1);
    k_gemm<256,64,1,1><<<640,256>>>(x1, w1+i*16384, b1+i*256,
                                    ln2_g+i*64, ln2_b+i*64, ffp);
    k_gemm<64,256,0,0><<<640,256>>>(ffp, w2+i*16384, b2+i*64,
                                    (const float*)0, (const float*)0, x2);
  }

  k_final<<<5000,128>>>(x1, x2, out_w, out_b, (float*)d_out);
}

// round 16
// speedup vs baseline: 1.3227x; 1.0297x over previous
#include <cuda_runtime.h>
#include <math.h>

#define NBATCH 16
#define LPAD 1280
#define LIN 1250
#define DM 64
#define NH 4
#define DH 16
#define NR 4        // hash rounds
#define BSZ 64      // bucket chunk size
#define NB 20       // buckets per round
#define NCH 80      // NR*NB chunks
#define BHH 64      // NBATCH*NH
#define MR 20480    // NBATCH*LPAD
#define FF 256

typedef unsigned long long ull;

__device__ __forceinline__ ull pack2(float lo, float hi){
  ull r; asm("mov.b64 %0,{%1,%2};" : "=l"(r) : "f"(lo), "f"(hi)); return r;
}
__device__ __forceinline__ void unpack2(ull a, float& lo, float& hi){
  asm("mov.b64 {%0,%1},%2;" : "=f"(lo), "=f"(hi) : "l"(a));
}
__device__ __forceinline__ void fma2(ull& d, ull a, ull b){
  asm("fma.rn.f32x2 %0,%1,%2,%0;" : "+l"(d) : "l"(a), "l"(b));
}
__device__ __forceinline__ void mul2(ull& d, ull a, ull b){
  asm("mul.rn.f32x2 %0,%1,%2;" : "=l"(d) : "l"(a), "l"(b));
}
__device__ __forceinline__ float hsum2(ull a){
  float lo, hi; unpack2(a, lo, hi); return lo + hi;
}

// ---------------- scratch (device globals; no allocation allowed) ----------------
__device__ float g_x1[MR*DM];
__device__ float g_x2[MR*DM];
__device__ float g_qk[BHH*LPAD*DH];
__device__ float g_v [BHH*LPAD*DH];
__device__ unsigned char g_bkt[BHH*NR*LPAD];
__device__ int   g_cnt[BHH*NR*8*NB];
__device__ short g_sj [BHH*NR*LPAD];
__device__ float g_o  [BHH*NR*LPAD*DH];
__device__ float g_lse[BHH*NR*LPAD];
__device__ float g_ffh[MR*FF];

// ---------------- embed: x = pad(wave^T) @ in_w + in_b ----------------
__global__ void k_embed(const float* __restrict__ wave, const float* __restrict__ in_w,
                        const float* __restrict__ in_b, float* __restrict__ x1,
                        float* __restrict__ x2){
  int gid = blockIdx.x*256 + threadIdx.x;       // 16*1280*64 total
  int d = gid & 63;
  int t = (gid >> 6) % LPAD;
  int b = gid / (LPAD*64);
  float val = in_b[d];
  if (t < LIN)
    val += wave[b*2*LIN + t]*in_w[d] + wave[b*2*LIN + LIN + t]*in_w[64+d];
  x1[gid] = val; x2[gid] = val;
}

__device__ __forceinline__ float gelu_f(float x){
  return 0.5f*x*(1.0f + erff(x*0.7071067811865476f));
}

// In-shared-tile layernorm, 32-row tile [68] stride: 8 threads/row, 8 cols each.
__device__ __forceinline__ void ln_tile32(float (*Xs)[68], int tid,
                                          const float* __restrict__ g,
                                          const float* __restrict__ b){
  int r = tid >> 3, q = tid & 7;
  float4* xp = (float4*)&Xs[r][q*8];
  float4 a0 = xp[0], a1 = xp[1];
  float s = a0.x+a0.y+a0.z+a0.w + a1.x+a1.y+a1.z+a1.w;
  s += __shfl_xor_sync(0xffffffffu, s, 1);
  s += __shfl_xor_sync(0xffffffffu, s, 2);
  s += __shfl_xor_sync(0xffffffffu, s, 4);
  float mean = s * (1.0f/64.0f);
  float d0=a0.x-mean, d1=a0.y-mean, d2=a0.z-mean, d3=a0.w-mean;
  float d4=a1.x-mean, d5=a1.y-mean, d6=a1.z-mean, d7=a1.w-mean;
  float sq = d0*d0+d1*d1+d2*d2+d3*d3+d4*d4+d5*d5+d6*d6+d7*d7;
  sq += __shfl_xor_sync(0xffffffffu, sq, 1);
  sq += __shfl_xor_sync(0xffffffffu, sq, 2);
  sq += __shfl_xor_sync(0xffffffffu, sq, 4);
  float inv = rsqrtf(sq*(1.0f/64.0f) + 1e-5f);
  float4 g0 = ((const float4*)(g + q*8))[0], g1 = ((const float4*)(g + q*8))[1];
  float4 b0 = ((const float4*)(b + q*8))[0], b1 = ((const float4*)(b + q*8))[1];
  float4 o0, o1;
  o0.x=d0*inv*g0.x+b0.x; o0.y=d1*inv*g0.y+b0.y; o0.z=d2*inv*g0.z+b0.z; o0.w=d3*inv*g0.w+b0.w;
  o1.x=d4*inv*g1.x+b1.x; o1.y=d5*inv*g1.y+b1.y; o1.z=d6*inv*g1.z+b1.z; o1.w=d7*inv*g1.w+b1.w;
  xp[0]=o0; xp[1]=o1;
}

// In-shared-tile layernorm, 64-row tile [68] stride: 4 threads/row, 16 cols each.
__device__ __forceinline__ void ln_tile64(float (*Xs)[68], int tid,
                                          const float* __restrict__ g,
                                          const float* __restrict__ b){
  int r = tid >> 2, q = tid & 3;
  float vals[16];
  float4* xp = (float4*)&Xs[r][q*16];
  #pragma unroll
  for (int i=0;i<4;i++){
    float4 f4 = xp[i];
    vals[4*i]=f4.x; vals[4*i+1]=f4.y; vals[4*i+2]=f4.z; vals[4*i+3]=f4.w;
  }
  float s = 0.f;
  #pragma unroll
  for (int f=0;f<16;f++) s += vals[f];
  s += __shfl_xor_sync(0xffffffffu, s, 1);
  s += __shfl_xor_sync(0xffffffffu, s, 2);
  float mean = s * (1.0f/64.0f);
  float sq = 0.f;
  #pragma unroll
  for (int f=0;f<16;f++){ float d = vals[f]-mean; sq += d*d; }
  sq += __shfl_xor_sync(0xffffffffu, sq, 1);
  sq += __shfl_xor_sync(0xffffffffu, sq, 2);
  float inv = rsqrtf(sq*(1.0f/64.0f) + 1e-5f);
  #pragma unroll
  for (int i=0;i<4;i++){
    float4 gg = ((const float4*)(g + q*16))[i];
    float4 bb = ((const float4*)(b + q*16))[i];
    float4 o;
    o.x = (vals[4*i]  -mean)*inv*gg.x + bb.x;
    o.y = (vals[4*i+1]-mean)*inv*gg.y + bb.y;
    o.z = (vals[4*i+2]-mean)*inv*gg.z + bb.z;
    o.w = (vals[4*i+3]-mean)*inv*gg.w + bb.w;
    xp[i] = o;
  }
}

// ---------------- fused LN1 + qk/v GEMM (f32x2 pair-column, flat Ws, head-split) --------
// (byte-identical to the 1066us R14 winner)
__global__ __launch_bounds__(256) void k_lnqkv(const float* __restrict__ X,
                           const float* __restrict__ lg, const float* __restrict__ lb,
                           const float* __restrict__ Wq,
                           const float* __restrict__ Wv, float* __restrict__ qk,
                           float* __restrict__ v){
  __shared__ float Xs[32][68];
  __shared__ float Wqs[4096];
  __shared__ float Wvs[4096];
  int tid = threadIdx.x;
  int row0 = blockIdx.x*32;
  int tx = tid & 15, ty = tid >> 4;
  for (int i=tid;i<512;i+=256){
    int r=i>>4, c=i&15;
    *(float4*)&Xs[r][4*c] = *(const float4*)(X + (size_t)(row0+r)*64 + 4*c);
  }
  for (int i=tid;i<4096;i+=256){ Wqs[i]=Wq[i]; Wvs[i]=Wv[i]; }
  __syncthreads();
  ln_tile32(Xs, tid, lg, lb);
  __syncthreads();
  ull aq[2][2]={{0ull,0ull},{0ull,0ull}};
  ull av[2][2]={{0ull,0ull},{0ull,0ull}};
  #pragma unroll 4
  for (int k=0;k<64;k++){
    float x0 = Xs[ty*2][k], x1 = Xs[ty*2+1][k];
    ull xx0 = pack2(x0,x0), xx1 = pack2(x1,x1);
    #pragma unroll
    for (int cc=0;cc<2;cc++){
      ull wq = *(const ull*)&Wqs[k*64 + 2*tx + 32*cc];
      ull wv = *(const ull*)&Wvs[k*64 + 2*tx + 32*cc];
      fma2(aq[0][cc], xx0, wq); fma2(aq[1][cc], xx1, wq);
      fma2(av[0][cc], xx0, wv); fma2(av[1][cc], xx1, wv);
    }
  }
  #pragma unroll
  for (int rr=0;rr<2;rr++){
    int m = row0 + ty*2 + rr;
    int b = m / LPAD, t = m % LPAD;
    #pragma unroll
    for (int cc=0;cc<2;cc++){
      int c = 2*tx + 32*cc;                      // output column 0..63
      int head = c >> 4, d0 = c & 15;            // pair stays within one head (c even)
      size_t base = ((size_t)(b*NH+head)*LPAD + t)*DH + d0;
      float lo, hi;
      unpack2(aq[rr][cc], lo, hi);
      *(float2*)(qk + base) = make_float2(lo, hi);
      unpack2(av[rr][cc], lo, hi);
      *(float2*)(v + base) = make_float2(lo, hi);
    }
  }
}

// ---------------- fused combine + output GEMM + residual (64-row, 4-row threads) --------
__global__ __launch_bounds__(256) void k_wo(const float* __restrict__ o,
                       const float* __restrict__ lse,
                       const float* __restrict__ W,
                       const float* __restrict__ bias, float* __restrict__ Y){
  __shared__ float Xs[64][68];
  __shared__ float Ws[4096];
  int tid = threadIdx.x;
  int row0 = blockIdx.x*64;
  int tx = tid & 15, ty = tid >> 4;
  for (int i=tid;i<4096;i+=256) Ws[i]=W[i];
  // combine hash rounds into Xs: thread -> (row r, head u, 16 cols)
  { int r = tid & 63, u = tid >> 6;              // u in 0..3 = head
    int c0 = u*16;
    int m = row0 + r; int b = m / LPAD, t = m % LPAD;
    int bh = b*NH + u;
    float ls[NR];
    #pragma unroll
    for (int rr=0;rr<NR;rr++) ls[rr] = lse[(size_t)(bh*NR+rr)*LPAD + t];
    float mx = fmaxf(fmaxf(ls[0],ls[1]), fmaxf(ls[2],ls[3]));
    float w[NR], s=0.f;
    #pragma unroll
    for (int rr=0;rr<NR;rr++){ w[rr]=__expf(ls[rr]-mx); s+=w[rr]; }
    float invs = 1.f/s;
    #pragma unroll
    for (int rr=0;rr<NR;rr++) w[rr] *= invs;
    const float* ob = o + ((size_t)(bh*NR)*LPAD + t)*DH;
    #pragma unroll
    for (int i=0;i<4;i++){
      float4 a = make_float4(0.f,0.f,0.f,0.f);
      #pragma unroll
      for (int rr=0;rr<NR;rr++){
        float4 ov = *(const float4*)(ob + (size_t)rr*LPAD*DH + 4*i);
        a.x += w[rr]*ov.x; a.y += w[rr]*ov.y; a.z += w[rr]*ov.z; a.w += w[rr]*ov.w;
      }
      *(float4*)&Xs[r][c0 + 4*i] = a;
    } }
  __syncthreads();
  ull acc[4][2];
  #pragma unroll
  for (int i=0;i<4;i++){ acc[i][0]=0ull; acc[i][1]=0ull; }
  #pragma unroll 4
  for (int k=0;k<64;k++){
    ull xx[4];
    #pragma unroll
    for (int i=0;i<4;i++){ float x = Xs[4*ty+i][k]; xx[i]=pack2(x,x); }
    #pragma unroll
    for (int cc=0;cc<2;cc++){
      ull w = *(const ull*)&Ws[k*64 + 2*tx + 32*cc];
      #pragma unroll
      for (int i=0;i<4;i++) fma2(acc[i][cc], xx[i], w);
    }
  }
  #pragma unroll
  for (int i=0;i<4;i++){
    int m = row0 + 4*ty + i;
    #pragma unroll
    for (int cc=0;cc<2;cc++){
      int c = 2*tx + 32*cc;
      float lo, hi;
      unpack2(acc[i][cc], lo, hi);
      float2* yp = (float2*)(Y + (size_t)m*64 + c);
      float2 prev = *yp;
      *yp = make_float2(prev.x + lo + bias[c], prev.y + hi + bias[c+1]);
    }
  }
}

// ---------------- FF part 1: LN2 + X@W1 + gelu (64-row x 64-col blocks, f32x2) ---------
__global__ __launch_bounds__(256) void k_ff1(const float* __restrict__ X,
                       const float* __restrict__ lg, const float* __restrict__ lb,
                       const float* __restrict__ W1, const float* __restrict__ b1,
                       float* __restrict__ H){
  __shared__ float Xs[64][68];
  __shared__ float Ws[4096];
  int tid = threadIdx.x;
  int row0 = blockIdx.x*64;
  int col0 = blockIdx.y*64;
  int tx = tid & 15, ty = tid >> 4;
  for (int i=tid;i<1024;i+=256){
    int r=i>>4, c=i&15;
    *(float4*)&Xs[r][4*c] = *(const float4*)(X + (size_t)(row0+r)*64 + 4*c);
  }
  for (int i=tid;i<4096;i+=256){
    int k=i>>6, c=i&63;
    Ws[i] = W1[(size_t)k*FF + col0 + c];
  }
  __syncthreads();
  ln_tile64(Xs, tid, lg, lb);
  __syncthreads();
  ull acc[4][2];
  #pragma unroll
  for (int i=0;i<4;i++){ acc[i][0]=0ull; acc[i][1]=0ull; }
  #pragma unroll 4
  for (int k=0;k<64;k++){
    ull xx[4];
    #pragma unroll
    for (int i=0;i<4;i++){ float x = Xs[4*ty+i][k]; xx[i]=pack2(x,x); }
    #pragma unroll
    for (int cc=0;cc<2;cc++){
      ull w = *(const ull*)&Ws[k*64 + 2*tx + 32*cc];
      #pragma unroll
      for (int i=0;i<4;i++) fma2(acc[i][cc], xx[i], w);
    }
  }
  #pragma unroll
  for (int i=0;i<4;i++){
    int m = row0 + 4*ty + i;
    #pragma unroll
    for (int cc=0;cc<2;cc++){
      int c = col0 + 2*tx + 32*cc;
      float lo, hi;
      unpack2(acc[i][cc], lo, hi);
      *(float2*)(H + (size_t)m*FF + c) =
        make_float2(gelu_f(lo + b1[c]), gelu_f(hi + b1[c+1]));
    }
  }
}

// ---------------- FF part 2: H@W2 + residual (64-row tiles, K=256, f32x2) --------------
__global__ __launch_bounds__(256) void k_ff2(const float* __restrict__ H,
                       const float* __restrict__ W2, const float* __restrict__ b2,
                       float* __restrict__ Y){
  __shared__ float Xs[64][68];
  __shared__ float Ws[4096];
  int tid = threadIdx.x;
  int row0 = blockIdx.x*64;
  int tx = tid & 15, ty = tid >> 4;
  ull acc[4][2];
  #pragma unroll
  for (int i=0;i<4;i++){ acc[i][0]=0ull; acc[i][1]=0ull; }
  for (int kc=0; kc<4; kc++){
    __syncthreads();
    for (int i=tid;i<1024;i+=256){
      int r=i>>4, c=i&15;
      *(float4*)&Xs[r][4*c] = *(const float4*)(H + (size_t)(row0+r)*FF + kc*64 + 4*c);
    }
    for (int i=tid;i<4096;i+=256){
      int k=i>>6, c=i&63;
      Ws[i] = W2[(size_t)(kc*64+k)*64 + c];
    }
    __syncthreads();
    #pragma unroll 4
    for (int k=0;k<64;k++){
      ull xx[4];
      #pragma unroll
      for (int i=0;i<4;i++){ float x = Xs[4*ty+i][k]; xx[i]=pack2(x,x); }
      #pragma unroll
      for (int cc=0;cc<2;cc++){
        ull w = *(const ull*)&Ws[k*64 + 2*tx + 32*cc];
        #pragma unroll
        for (int i=0;i<4;i++) fma2(acc[i][cc], xx[i], w);
      }
    }
  }
  #pragma unroll
  for (int i=0;i<4;i++){
    int m = row0 + 4*ty + i;
    #pragma unroll
    for (int cc=0;cc<2;cc++){
      int c = 2*tx + 32*cc;
      float lo, hi;
      unpack2(acc[i][cc], lo, hi);
      float2* yp = (float2*)(Y + (size_t)m*64 + c);
      float2 prev = *yp;
      *yp = make_float2(prev.x + lo + b2[c], prev.y + hi + b2[c+1]);
    }
  }
}

// ---------------- LSH hashing + per-segment histogram (fused, proven) ----------------
__global__ void k_hashcount(const float* __restrict__ qk, const float* __restrict__ rot,
                            unsigned char* __restrict__ bkt, int* __restrict__ cnt){
  __shared__ float rs[640];                      // rot (16,4,10)
  __shared__ int c[NR][NB];
  int tid = threadIdx.x;                         // 160
  int seg = blockIdx.x, bh = blockIdx.y;
  for (int i=tid;i<640;i+=160) rs[i]=rot[i];
  if (tid < NR*NB) ((int*)c)[tid] = 0;
  __syncthreads();
  int t = seg*160 + tid;
  const float4* qr = reinterpret_cast<const float4*>(qk + ((size_t)bh*LPAD + t)*DH);
  float q[16];
  #pragma unroll
  for (int i=0;i<4;i++){ float4 f4=qr[i]; q[4*i]=f4.x; q[4*i+1]=f4.y; q[4*i+2]=f4.z; q[4*i+3]=f4.w; }
  #pragma unroll
  for (int r=0;r<NR;r++){
    float p[10];
    #pragma unroll
    for (int i=0;i<10;i++){
      float s=0.f;
      #pragma unroll
      for (int f=0;f<16;f++) s += q[f]*rs[f*40 + r*10 + i];
      p[i]=s;
    }
    float best=-3.402823e38f; int bi=0;
    #pragma unroll
    for (int idx=0; idx<20; idx++){
      float val = (idx<10)? p[idx] : -p[idx-10];
      if (val>best){best=val;bi=idx;}           // first-max tie-break like jnp.argmax
    }
    bkt[((size_t)bh*NR + r)*LPAD + t] = (unsigned char)bi;
    atomicAdd(&c[r][bi], 1);
  }
  __syncthreads();
  if (tid < NR*NB){
    int r = tid / NB, b = tid % NB;
    cnt[((size_t)((bh*NR+r)*8 + seg))*NB + b] = c[r][b];
  }
}

// ---------------- fused prefix scan + stable scatter (uchar4 loads) ----------------
__global__ __launch_bounds__(640) void k_psort(const int* __restrict__ cnt,
                         const unsigned char* __restrict__ bkt,
                         short* __restrict__ sj){
  __shared__ int ws[20];
  __shared__ int offs[32][NB];                   // [(r,seg)][b]
  int bh = blockIdx.x;
  int i = threadIdx.x;                           // 640
  int r = i/160, b = (i%160)/8, seg = i%8;       // scan order (r,b,seg)
  int idx = ((bh*NR + r)*8 + seg)*NB + b;
  int v = cnt[idx];
  int lane = i & 31, w = i >> 5;
  int s = v;
  #pragma unroll
  for (int o=1;o<32;o<<=1){ int t=__shfl_up_sync(0xffffffffu, s, o); if (lane>=o) s+=t; }
  if (lane==31) ws[w]=s;
  __syncthreads();
  if (i < 32){
    int t = (i<20)? ws[i] : 0;
    #pragma unroll
    for (int o=1;o<32;o<<=1){ int u=__shfl_up_sync(0xffffffffu, t, o); if (i>=o) t+=u; }
    if (i<20) ws[i]=t;
  }
  __syncthreads();
  int base = (w>0)? ws[w-1] : 0;
  offs[r*8+seg][b] = base + s - v;
  __syncthreads();
  if (i < 32){
    int r2 = i >> 3, s2 = i & 7;
    const uchar4* p4 = (const uchar4*)(bkt + ((size_t)bh*NR + r2)*LPAD + s2*160);
    short* sjb = sj + (size_t)bh*NR*LPAD;
    int basej = r2*LPAD + s2*160;
    int* cc = offs[i];
    #pragma unroll 2
    for (int k=0;k<40;k++){
      uchar4 u = p4[k];
      int s3;
      s3 = cc[u.x]++; sjb[s3] = (short)(basej + 4*k);
      s3 = cc[u.y]++; sjb[s3] = (short)(basej + 4*k + 1);
      s3 = cc[u.z]++; sjb[s3] = (short)(basej + 4*k + 2);
      s3 = cc[u.w]++; sjb[s3] = (short)(basej + 4*k + 3);
    }
  }
}

// ---------------- chunked LSH attention, flash softmax, split-K x2 (proven R8) ---------
__global__ __launch_bounds__(128) void k_attn(const float* __restrict__ qk,
                       const float* __restrict__ v,
                       const short* __restrict__ sj, float* __restrict__ o,
                       float* __restrict__ lse){
  __shared__ float Ks[128][16];
  __shared__ float Vs[128][16];
  __shared__ int   tks[128];
  __shared__ float Pm[64], Pl[64];
  __shared__ float Pacc[64][16];
  int c = blockIdx.x, bh = blockIdx.y, tid = threadIdx.x;  // 128 threads
  int qi = tid & 63, half = tid >> 6;
  const short* sjb = sj + (size_t)bh*NR*LPAD;
  int jq = sjb[c*BSZ + qi];
  int tq = jq % LPAD, rq = jq / LPAD;
  ull qv[8];
  { const ulonglong2* qr = reinterpret_cast<const ulonglong2*>(qk + ((size_t)bh*LPAD + tq)*DH);
    #pragma unroll
    for (int i=0;i<4;i++){ ulonglong2 u=qr[i]; qv[2*i]=u.x; qv[2*i+1]=u.y; } }
  int prev = (c + NCH - 1) % NCH;
  { int kk = tid;
    int cc = (kk<64)? c : prev;
    int jk = sjb[cc*BSZ + (kk&63)];
    int tk = jk % LPAD;
    float kvv[16];
    { const float4* kr = reinterpret_cast<const float4*>(qk + ((size_t)bh*LPAD + tk)*DH);
      #pragma unroll
      for (int i=0;i<4;i++){ float4 f4=kr[i]; kvv[4*i]=f4.x; kvv[4*i+1]=f4.y; kvv[4*i+2]=f4.z; kvv[4*i+3]=f4.w; } }
    float ss=0.f;
    #pragma unroll
    for (int f=0;f<16;f++) ss += kvv[f]*kvv[f];
    float inv = 1.0f / fmaxf(sqrtf(ss), 1e-12f);
    float4* kd = (float4*)&Ks[kk][0];
    #pragma unroll
    for (int i=0;i<4;i++){
      float4 f4; f4.x=kvv[4*i]*inv; f4.y=kvv[4*i+1]*inv; f4.z=kvv[4*i+2]*inv; f4.w=kvv[4*i+3]*inv;
      kd[i]=f4;
    }
    { const float4* vr = reinterpret_cast<const float4*>(v + ((size_t)bh*LPAD + tk)*DH);
      float4* vd = (float4*)&Vs[kk][0];
      #pragma unroll
      for (int i=0;i<4;i++) vd[i]=vr[i];
    }
    tks[kk]=tk;
  }
  __syncthreads();
  float m=-3.0e38f, l=0.f;
  ull acc2[8];
  #pragma unroll
  for (int f=0;f<8;f++) acc2[f]=0ull;
  int jbase = half << 6;
  #pragma unroll 2
  for (int jj=0;jj<64;jj++){
    int j = jbase + jj;
    const ulonglong2* kr = (const ulonglong2*)&Ks[j][0];
    ull d2 = 0ull;
    #pragma unroll
    for (int i=0;i<4;i++){
      ulonglong2 u = kr[i];
      fma2(d2, qv[2*i],   u.x);
      fma2(d2, qv[2*i+1], u.y);
    }
    float d = hsum2(d2) * 0.25f;                 // DH^-0.5
    if (tks[j]==tq) d = -50000.0f;               // SELF_ATTN_VAL
    if (d>m){
      float sc=__expf(m-d);
      l*=sc;
      ull sc2 = pack2(sc,sc);
      #pragma unroll
      for (int f=0;f<8;f++) mul2(acc2[f], acc2[f], sc2);
      m=d;
    }
    float p=__expf(d-m);
    l += p;
    ull p2 = pack2(p,p);
    const ulonglong2* vr = (const ulonglong2*)&Vs[j][0];
    #pragma unroll
    for (int i=0;i<4;i++){
      ulonglong2 u = vr[i];
      fma2(acc2[2*i],   p2, u.x);
      fma2(acc2[2*i+1], p2, u.y);
    }
  }
  if (half){
    Pm[qi]=m; Pl[qi]=l;
    float tmp[16];
    #pragma unroll
    for (int f=0;f<8;f++) unpack2(acc2[f], tmp[2*f], tmp[2*f+1]);
    float4* pa = (float4*)Pacc[qi];
    #pragma unroll
    for (int i=0;i<4;i++){
      float4 f4; f4.x=tmp[4*i]; f4.y=tmp[4*i+1]; f4.z=tmp[4*i+2]; f4.w=tmp[4*i+3];
      pa[i]=f4;
    }
  }
  __syncthreads();
  if (!half){
    float m2 = Pm[qi], l2 = Pl[qi];
    float M = fmaxf(m, m2);
    float s1 = __expf(m - M), s2 = __expf(m2 - M);
    float L = l*s1 + l2*s2;
    float invl = 1.0f/L;
    float out[16];
    #pragma unroll
    for (int f=0;f<8;f++) unpack2(acc2[f], out[2*f], out[2*f+1]);
    const float4* pa = (const float4*)Pacc[qi];
    float4* op = (float4*)(o + ((size_t)(bh*NR + rq)*LPAD + tq)*DH);  // scatter == undo_sort
    #pragma unroll
    for (int i=0;i<4;i++){
      float4 p = pa[i];
      float4 f4;
      f4.x = (out[4*i+0]*s1 + p.x*s2)*invl;
      f4.y = (out[4*i+1]*s1 + p.y*s2)*invl;
      f4.z = (out[4*i+2]*s1 + p.z*s2)*invl;
      f4.w = (out[4*i+3]*s1 + p.w*s2)*invl;
      op[i]=f4;
    }
    lse[(size_t)(bh*NR+rq)*LPAD + tq] = M + logf(L);
  }
}

// ---------------- final: y = ((x1+x2)*0.5) @ out_w + out_b, trim to 1250 ----------------
__global__ void k_final(const float* __restrict__ x1, const float* __restrict__ x2,
                        const float* __restrict__ ow, const float* __restrict__ ob,
                        float* __restrict__ y){
  int row  = blockIdx.x*4 + (threadIdx.x>>5);    // 16*1250 rows
  int lane = threadIdx.x & 31;
  int b = row / LIN, t = row % LIN;
  size_t base = ((size_t)b*LPAD + t)*DM;
  float s = (x1[base+lane]+x2[base+lane])*0.5f*ow[lane]
          + (x1[base+lane+32]+x2[base+lane+32])*0.5f*ow[lane+32];
  #pragma unroll
  for (int o2=16;o2>0;o2>>=1) s += __shfl_xor_sync(0xffffffffu, s, o2);
  if (lane==0) y[row] = s + ob[0];
}

// ---------------- host launcher ----------------
extern "C" void kernel_launch(void* const* d_in, const int* in_sizes, int n_in,
                              void* d_out, int out_size){
  const float* wave  = (const float*)d_in[0];
  const float* in_w  = (const float*)d_in[1];
  const float* in_b  = (const float*)d_in[2];
  const float* ln1_g = (const float*)d_in[3];
  const float* ln1_b = (const float*)d_in[4];
  const float* wqk   = (const float*)d_in[5];
  const float* wv    = (const float*)d_in[6];
  const float* wo_w  = (const float*)d_in[7];
  const float* wo_b  = (const float*)d_in[8];
  const float* rot   = (const float*)d_in[9];
  const float* ln2_g = (const float*)d_in[10];
  const float* ln2_b = (const float*)d_in[11];
  const float* w1    = (const float*)d_in[12];
  const float* b1    = (const float*)d_in[13];
  const float* w2    = (const float*)d_in[14];
  const float* b2    = (const float*)d_in[15];
  const float* out_w = (const float*)d_in[16];
  const float* out_b = (const float*)d_in[17];

  float *x1,*x2,*qkp,*vp,*op,*lsp,*ffp;
  unsigned char* bktp; int *cntp; short* sjp;
  cudaGetSymbolAddress((void**)&x1,  g_x1);
  cudaGetSymbolAddress((void**)&x2,  g_x2);
  cudaGetSymbolAddress((void**)&qkp, g_qk);
  cudaGetSymbolAddress((void**)&vp,  g_v);
  cudaGetSymbolAddress((void**)&bktp,g_bkt);
  cudaGetSymbolAddress((void**)&cntp,g_cnt);
  cudaGetSymbolAddress((void**)&sjp, g_sj);
  cudaGetSymbolAddress((void**)&op,  g_o);
  cudaGetSymbolAddress((void**)&lsp, g_lse);
  cudaGetSymbolAddress((void**)&ffp, g_ffh);

  k_embed<<<5120,256>>>(wave, in_w, in_b, x1, x2);

  for (int i=0;i<4;i++){
    k_lnqkv<<<640,256>>>(x2, ln1_g+i*64, ln1_b+i*64, wqk+i*4096, wv+i*4096, qkp, vp);
    k_hashcount<<<dim3(8,64),160>>>(qkp, rot+i*640, bktp, cntp);
    k_psort<<<64,640>>>(cntp, bktp, sjp);
    k_attn<<<dim3(80,64),128>>>(qkp, vp, sjp, op, lsp);
    k_wo<<<320,256>>>(op, lsp, wo_w+i*4096, wo_b+i*64, x1);
    k_ff1<<<dim3(320,4),256>>>(x1, ln2_g+i*64, ln2_b+i*64, w1+i*16384, b1+i*256, ffp);
    k_ff2<<<320,256>>>(ffp, w2+i*16384, b2+i*64, x2);
  }

  k_final<<<5000,128>>>(x1, x2, out_w, out_b, (float*)d_out);
}

// round 17
// speedup vs baseline: 1.3672x; 1.0337x over previous
#include <cuda_runtime.h>
#include <math.h>

#define NBATCH 16
#define LPAD 1280
#define LIN 1250
#define DM 64
#define NH 4
#define DH 16
#define NR 4        // hash rounds
#define BSZ 64      // bucket chunk size
#define NB 20       // buckets per round
#define NCH 80      // NR*NB chunks
#define BHH 64      // NBATCH*NH
#define MR 20480    // NBATCH*LPAD
#define FF 256

typedef unsigned long long ull;

__device__ __forceinline__ ull pack2(float lo, float hi){
  ull r; asm("mov.b64 %0,{%1,%2};" : "=l"(r) : "f"(lo), "f"(hi)); return r;
}
__device__ __forceinline__ void unpack2(ull a, float& lo, float& hi){
  asm("mov.b64 {%0,%1},%2;" : "=f"(lo), "=f"(hi) : "l"(a));
}
__device__ __forceinline__ void fma2(ull& d, ull a, ull b){
  asm("fma.rn.f32x2 %0,%1,%2,%0;" : "+l"(d) : "l"(a), "l"(b));
}
__device__ __forceinline__ void mul2(ull& d, ull a, ull b){
  asm("mul.rn.f32x2 %0,%1,%2;" : "=l"(d) : "l"(a), "l"(b));
}
__device__ __forceinline__ float hsum2(ull a){
  float lo, hi; unpack2(a, lo, hi); return lo + hi;
}

// ---------------- scratch (device globals; no allocation allowed) ----------------
__device__ float g_x1[MR*DM];
__device__ float g_x2[MR*DM];
__device__ float g_qk[BHH*LPAD*DH];
__device__ float g_v [BHH*LPAD*DH];
__device__ unsigned char g_bkt[BHH*NR*LPAD];
__device__ int   g_cnt[BHH*NR*8*NB];
__device__ short g_sj [BHH*NR*LPAD];
__device__ float g_o  [BHH*NR*LPAD*DH];
__device__ float g_lse[BHH*NR*LPAD];
__device__ float g_ffh[MR*FF];

// ---------------- embed: x = pad(wave^T) @ in_w + in_b ----------------
__global__ void k_embed(const float* __restrict__ wave, const float* __restrict__ in_w,
                        const float* __restrict__ in_b, float* __restrict__ x1,
                        float* __restrict__ x2){
  int gid = blockIdx.x*256 + threadIdx.x;       // 16*1280*64 total
  int d = gid & 63;
  int t = (gid >> 6) % LPAD;
  int b = gid / (LPAD*64);
  float val = in_b[d];
  if (t < LIN)
    val += wave[b*2*LIN + t]*in_w[d] + wave[b*2*LIN + LIN + t]*in_w[64+d];
  x1[gid] = val; x2[gid] = val;
}

__device__ __forceinline__ float gelu_f(float x){
  return 0.5f*x*(1.0f + erff(x*0.7071067811865476f));
}

// In-shared-tile layernorm, 64-row tile [68] stride: 4 threads/row, 16 cols each.
__device__ __forceinline__ void ln_tile64(float (*Xs)[68], int tid,
                                          const float* __restrict__ g,
                                          const float* __restrict__ b){
  int r = tid >> 2, q = tid & 3;
  float vals[16];
  float4* xp = (float4*)&Xs[r][q*16];
  #pragma unroll
  for (int i=0;i<4;i++){
    float4 f4 = xp[i];
    vals[4*i]=f4.x; vals[4*i+1]=f4.y; vals[4*i+2]=f4.z; vals[4*i+3]=f4.w;
  }
  float s = 0.f;
  #pragma unroll
  for (int f=0;f<16;f++) s += vals[f];
  s += __shfl_xor_sync(0xffffffffu, s, 1);
  s += __shfl_xor_sync(0xffffffffu, s, 2);
  float mean = s * (1.0f/64.0f);
  float sq = 0.f;
  #pragma unroll
  for (int f=0;f<16;f++){ float d = vals[f]-mean; sq += d*d; }
  sq += __shfl_xor_sync(0xffffffffu, sq, 1);
  sq += __shfl_xor_sync(0xffffffffu, sq, 2);
  float inv = rsqrtf(sq*(1.0f/64.0f) + 1e-5f);
  #pragma unroll
  for (int i=0;i<4;i++){
    float4 gg = ((const float4*)(g + q*16))[i];
    float4 bb = ((const float4*)(b + q*16))[i];
    float4 o;
    o.x = (vals[4*i]  -mean)*inv*gg.x + bb.x;
    o.y = (vals[4*i+1]-mean)*inv*gg.y + bb.y;
    o.z = (vals[4*i+2]-mean)*inv*gg.z + bb.z;
    o.w = (vals[4*i+3]-mean)*inv*gg.w + bb.w;
    xp[i] = o;
  }
}

// ---------------- fused LN1 + qk/v GEMM (64-row, 4-row threads, f32x2, dyn smem) --------
__global__ __launch_bounds__(256) void k_lnqkv(const float* __restrict__ X,
                           const float* __restrict__ lg, const float* __restrict__ lb,
                           const float* __restrict__ Wq,
                           const float* __restrict__ Wv, float* __restrict__ qk,
                           float* __restrict__ v){
  extern __shared__ float sm[];
  float (*Xs)[68] = (float(*)[68])sm;            // 64x68
  float* Wqs = sm + 64*68;                       // 4096
  float* Wvs = sm + 64*68 + 4096;                // 4096
  int tid = threadIdx.x;
  int row0 = blockIdx.x*64;
  int tx = tid & 15, ty = tid >> 4;
  for (int i=tid;i<1024;i+=256){
    int r=i>>4, c=i&15;
    *(float4*)&Xs[r][4*c] = *(const float4*)(X + (size_t)(row0+r)*64 + 4*c);
  }
  for (int i=tid;i<4096;i+=256){ Wqs[i]=Wq[i]; Wvs[i]=Wv[i]; }
  __syncthreads();
  ln_tile64(Xs, tid, lg, lb);
  __syncthreads();
  ull aq[4][2], av[4][2];
  #pragma unroll
  for (int i=0;i<4;i++){ aq[i][0]=0ull; aq[i][1]=0ull; av[i][0]=0ull; av[i][1]=0ull; }
  #pragma unroll 4
  for (int k=0;k<64;k++){
    ull xx[4];
    #pragma unroll
    for (int i=0;i<4;i++){ float x = Xs[4*ty+i][k]; xx[i]=pack2(x,x); }
    #pragma unroll
    for (int cc=0;cc<2;cc++){
      ull wq = *(const ull*)&Wqs[k*64 + 2*tx + 32*cc];
      ull wv = *(const ull*)&Wvs[k*64 + 2*tx + 32*cc];
      #pragma unroll
      for (int i=0;i<4;i++){
        fma2(aq[i][cc], xx[i], wq);
        fma2(av[i][cc], xx[i], wv);
      }
    }
  }
  #pragma unroll
  for (int i=0;i<4;i++){
    int m = row0 + 4*ty + i;
    int b = m / LPAD, t = m % LPAD;
    #pragma unroll
    for (int cc=0;cc<2;cc++){
      int c = 2*tx + 32*cc;                      // output column 0..63
      int head = c >> 4, d0 = c & 15;            // pair stays within one head (c even)
      size_t base = ((size_t)(b*NH+head)*LPAD + t)*DH + d0;
      float lo, hi;
      unpack2(aq[i][cc], lo, hi);
      *(float2*)(qk + base) = make_float2(lo, hi);
      unpack2(av[i][cc], lo, hi);
      *(float2*)(v + base) = make_float2(lo, hi);
    }
  }
}

// ---------------- fused combine + output GEMM + residual (64-row, 4-row threads) --------
__global__ __launch_bounds__(256) void k_wo(const float* __restrict__ o,
                       const float* __restrict__ lse,
                       const float* __restrict__ W,
                       const float* __restrict__ bias, float* __restrict__ Y){
  __shared__ float Xs[64][68];
  __shared__ float Ws[4096];
  int tid = threadIdx.x;
  int row0 = blockIdx.x*64;
  int tx = tid & 15, ty = tid >> 4;
  for (int i=tid;i<4096;i+=256) Ws[i]=W[i];
  // combine hash rounds into Xs: thread -> (row r, head u, 16 cols)
  { int r = tid & 63, u = tid >> 6;              // u in 0..3 = head
    int c0 = u*16;
    int m = row0 + r; int b = m / LPAD, t = m % LPAD;
    int bh = b*NH + u;
    float ls[NR];
    #pragma unroll
    for (int rr=0;rr<NR;rr++) ls[rr] = lse[(size_t)(bh*NR+rr)*LPAD + t];
    float mx = fmaxf(fmaxf(ls[0],ls[1]), fmaxf(ls[2],ls[3]));
    float w[NR], s=0.f;
    #pragma unroll
    for (int rr=0;rr<NR;rr++){ w[rr]=__expf(ls[rr]-mx); s+=w[rr]; }
    float invs = 1.f/s;
    #pragma unroll
    for (int rr=0;rr<NR;rr++) w[rr] *= invs;
    const float* ob = o + ((size_t)(bh*NR)*LPAD + t)*DH;
    #pragma unroll
    for (int i=0;i<4;i++){
      float4 a = make_float4(0.f,0.f,0.f,0.f);
      #pragma unroll
      for (int rr=0;rr<NR;rr++){
        float4 ov = *(const float4*)(ob + (size_t)rr*LPAD*DH + 4*i);
        a.x += w[rr]*ov.x; a.y += w[rr]*ov.y; a.z += w[rr]*ov.z; a.w += w[rr]*ov.w;
      }
      *(float4*)&Xs[r][c0 + 4*i] = a;
    } }
  __syncthreads();
  ull acc[4][2];
  #pragma unroll
  for (int i=0;i<4;i++){ acc[i][0]=0ull; acc[i][1]=0ull; }
  #pragma unroll 4
  for (int k=0;k<64;k++){
    ull xx[4];
    #pragma unroll
    for (int i=0;i<4;i++){ float x = Xs[4*ty+i][k]; xx[i]=pack2(x,x); }
    #pragma unroll
    for (int cc=0;cc<2;cc++){
      ull w = *(const ull*)&Ws[k*64 + 2*tx + 32*cc];
      #pragma unroll
      for (int i=0;i<4;i++) fma2(acc[i][cc], xx[i], w);
    }
  }
  #pragma unroll
  for (int i=0;i<4;i++){
    int m = row0 + 4*ty + i;
    #pragma unroll
    for (int cc=0;cc<2;cc++){
      int c = 2*tx + 32*cc;
      float lo, hi;
      unpack2(acc[i][cc], lo, hi);
      float2* yp = (float2*)(Y + (size_t)m*64 + c);
      float2 prev = *yp;
      *yp = make_float2(prev.x + lo + bias[c], prev.y + hi + bias[c+1]);
    }
  }
}

// ---------------- FF part 1: LN2 + X@W1 + gelu (64-row x 64-col blocks, f32x2) ---------
__global__ __launch_bounds__(256) void k_ff1(const float* __restrict__ X,
                       const float* __restrict__ lg, const float* __restrict__ lb,
                       const float* __restrict__ W1, const float* __restrict__ b1,
                       float* __restrict__ H){
  __shared__ float Xs[64][68];
  __shared__ float Ws[4096];
  int tid = threadIdx.x;
  int row0 = blockIdx.x*64;
  int col0 = blockIdx.y*64;
  int tx = tid & 15, ty = tid >> 4;
  for (int i=tid;i<1024;i+=256){
    int r=i>>4, c=i&15;
    *(float4*)&Xs[r][4*c] = *(const float4*)(X + (size_t)(row0+r)*64 + 4*c);
  }
  for (int i=tid;i<4096;i+=256){
    int k=i>>6, c=i&63;
    Ws[i] = W1[(size_t)k*FF + col0 + c];
  }
  __syncthreads();
  ln_tile64(Xs, tid, lg, lb);
  __syncthreads();
  ull acc[4][2];
  #pragma unroll
  for (int i=0;i<4;i++){ acc[i][0]=0ull; acc[i][1]=0ull; }
  #pragma unroll 4
  for (int k=0;k<64;k++){
    ull xx[4];
    #pragma unroll
    for (int i=0;i<4;i++){ float x = Xs[4*ty+i][k]; xx[i]=pack2(x,x); }
    #pragma unroll
    for (int cc=0;cc<2;cc++){
      ull w = *(const ull*)&Ws[k*64 + 2*tx + 32*cc];
      #pragma unroll
      for (int i=0;i<4;i++) fma2(acc[i][cc], xx[i], w);
    }
  }
  #pragma unroll
  for (int i=0;i<4;i++){
    int m = row0 + 4*ty + i;
    #pragma unroll
    for (int cc=0;cc<2;cc++){
      int c = col0 + 2*tx + 32*cc;
      float lo, hi;
      unpack2(acc[i][cc], lo, hi);
      *(float2*)(H + (size_t)m*FF + c) =
        make_float2(gelu_f(lo + b1[c]), gelu_f(hi + b1[c+1]));
    }
  }
}

// ---------------- FF part 2: H@W2 + residual (64-row tiles, K=256, f32x2) --------------
__global__ __launch_bounds__(256) void k_ff2(const float* __restrict__ H,
                       const float* __restrict__ W2, const float* __restrict__ b2,
                       float* __restrict__ Y){
  __shared__ float Xs[64][68];
  __shared__ float Ws[4096];
  int tid = threadIdx.x;
  int row0 = blockIdx.x*64;
  int tx = tid & 15, ty = tid >> 4;
  ull acc[4][2];
  #pragma unroll
  for (int i=0;i<4;i++){ acc[i][0]=0ull; acc[i][1]=0ull; }
  for (int kc=0; kc<4; kc++){
    __syncthreads();
    for (int i=tid;i<1024;i+=256){
      int r=i>>4, c=i&15;
      *(float4*)&Xs[r][4*c] = *(const float4*)(H + (size_t)(row0+r)*FF + kc*64 + 4*c);
    }
    for (int i=tid;i<4096;i+=256){
      int k=i>>6, c=i&63;
      Ws[i] = W2[(size_t)(kc*64+k)*64 + c];
    }
    __syncthreads();
    #pragma unroll 4
    for (int k=0;k<64;k++){
      ull xx[4];
      #pragma unroll
      for (int i=0;i<4;i++){ float x = Xs[4*ty+i][k]; xx[i]=pack2(x,x); }
      #pragma unroll
      for (int cc=0;cc<2;cc++){
        ull w = *(const ull*)&Ws[k*64 + 2*tx + 32*cc];
        #pragma unroll
        for (int i=0;i<4;i++) fma2(acc[i][cc], xx[i], w);
      }
    }
  }
  #pragma unroll
  for (int i=0;i<4;i++){
    int m = row0 + 4*ty + i;
    #pragma unroll
    for (int cc=0;cc<2;cc++){
      int c = 2*tx + 32*cc;
      float lo, hi;
      unpack2(acc[i][cc], lo, hi);
      float2* yp = (float2*)(Y + (size_t)m*64 + c);
      float2 prev = *yp;
      *yp = make_float2(prev.x + lo + b2[c], prev.y + hi + b2[c+1]);
    }
  }
}

// ---------------- LSH hashing + per-segment histogram (fused, proven) ----------------
__global__ void k_hashcount(const float* __restrict__ qk, const float* __restrict__ rot,
                            unsigned char* __restrict__ bkt, int* __restrict__ cnt){
  __shared__ float rs[640];                      // rot (16,4,10)
  __shared__ int c[NR][NB];
  int tid = threadIdx.x;                         // 160
  int seg = blockIdx.x, bh = blockIdx.y;
  for (int i=tid;i<640;i+=160) rs[i]=rot[i];
  if (tid < NR*NB) ((int*)c)[tid] = 0;
  __syncthreads();
  int t = seg*160 + tid;
  const float4* qr = reinterpret_cast<const float4*>(qk + ((size_t)bh*LPAD + t)*DH);
  float q[16];
  #pragma unroll
  for (int i=0;i<4;i++){ float4 f4=qr[i]; q[4*i]=f4.x; q[4*i+1]=f4.y; q[4*i+2]=f4.z; q[4*i+3]=f4.w; }
  #pragma unroll
  for (int r=0;r<NR;r++){
    float p[10];
    #pragma unroll
    for (int i=0;i<10;i++){
      float s=0.f;
      #pragma unroll
      for (int f=0;f<16;f++) s += q[f]*rs[f*40 + r*10 + i];
      p[i]=s;
    }
    float best=-3.402823e38f; int bi=0;
    #pragma unroll
    for (int idx=0; idx<20; idx++){
      float val = (idx<10)? p[idx] : -p[idx-10];
      if (val>best){best=val;bi=idx;}           // first-max tie-break like jnp.argmax
    }
    bkt[((size_t)bh*NR + r)*LPAD + t] = (unsigned char)bi;
    atomicAdd(&c[r][bi], 1);
  }
  __syncthreads();
  if (tid < NR*NB){
    int r = tid / NB, b = tid % NB;
    cnt[((size_t)((bh*NR+r)*8 + seg))*NB + b] = c[r][b];
  }
}

// ---------------- fused prefix scan + stable scatter (uchar4 loads) ----------------
__global__ __launch_bounds__(640) void k_psort(const int* __restrict__ cnt,
                         const unsigned char* __restrict__ bkt,
                         short* __restrict__ sj){
  __shared__ int ws[20];
  __shared__ int offs[32][NB];                   // [(r,seg)][b]
  int bh = blockIdx.x;
  int i = threadIdx.x;                           // 640
  int r = i/160, b = (i%160)/8, seg = i%8;       // scan order (r,b,seg)
  int idx = ((bh*NR + r)*8 + seg)*NB + b;
  int v = cnt[idx];
  int lane = i & 31, w = i >> 5;
  int s = v;
  #pragma unroll
  for (int o=1;o<32;o<<=1){ int t=__shfl_up_sync(0xffffffffu, s, o); if (lane>=o) s+=t; }
  if (lane==31) ws[w]=s;
  __syncthreads();
  if (i < 32){
    int t = (i<20)? ws[i] : 0;
    #pragma unroll
    for (int o=1;o<32;o<<=1){ int u=__shfl_up_sync(0xffffffffu, t, o); if (i>=o) t+=u; }
    if (i<20) ws[i]=t;
  }
  __syncthreads();
  int base = (w>0)? ws[w-1] : 0;
  offs[r*8+seg][b] = base + s - v;
  __syncthreads();
  if (i < 32){
    int r2 = i >> 3, s2 = i & 7;
    const uchar4* p4 = (const uchar4*)(bkt + ((size_t)bh*NR + r2)*LPAD + s2*160);
    short* sjb = sj + (size_t)bh*NR*LPAD;
    int basej = r2*LPAD + s2*160;
    int* cc = offs[i];
    #pragma unroll 2
    for (int k=0;k<40;k++){
      uchar4 u = p4[k];
      int s3;
      s3 = cc[u.x]++; sjb[s3] = (short)(basej + 4*k);
      s3 = cc[u.y]++; sjb[s3] = (short)(basej + 4*k + 1);
      s3 = cc[u.z]++; sjb[s3] = (short)(basej + 4*k + 2);
      s3 = cc[u.w]++; sjb[s3] = (short)(basej + 4*k + 3);
    }
  }
}

// ---------------- chunked LSH attention, flash softmax, split-K x2 (proven R8) ---------
__global__ __launch_bounds__(128) void k_attn(const float* __restrict__ qk,
                       const float* __restrict__ v,
                       const short* __restrict__ sj, float* __restrict__ o,
                       float* __restrict__ lse){
  __shared__ float Ks[128][16];
  __shared__ float Vs[128][16];
  __shared__ int   tks[128];
  __shared__ float Pm[64], Pl[64];
  __shared__ float Pacc[64][16];
  int c = blockIdx.x, bh = blockIdx.y, tid = threadIdx.x;  // 128 threads
  int qi = tid & 63, half = tid >> 6;
  const short* sjb = sj + (size_t)bh*NR*LPAD;
  int jq = sjb[c*BSZ + qi];
  int tq = jq % LPAD, rq = jq / LPAD;
  ull qv[8];
  { const ulonglong2* qr = reinterpret_cast<const ulonglong2*>(qk + ((size_t)bh*LPAD + tq)*DH);
    #pragma unroll
    for (int i=0;i<4;i++){ ulonglong2 u=qr[i]; qv[2*i]=u.x; qv[2*i+1]=u.y; } }
  int prev = (c + NCH - 1) % NCH;
  { int kk = tid;
    int cc = (kk<64)? c : prev;
    int jk = sjb[cc*BSZ + (kk&63)];
    int tk = jk % LPAD;
    float kvv[16];
    { const float4* kr = reinterpret_cast<const float4*>(qk + ((size_t)bh*LPAD + tk)*DH);
      #pragma unroll
      for (int i=0;i<4;i++){ float4 f4=kr[i]; kvv[4*i]=f4.x; kvv[4*i+1]=f4.y; kvv[4*i+2]=f4.z; kvv[4*i+3]=f4.w; } }
    float ss=0.f;
    #pragma unroll
    for (int f=0;f<16;f++) ss += kvv[f]*kvv[f];
    float inv = 1.0f / fmaxf(sqrtf(ss), 1e-12f);
    float4* kd = (float4*)&Ks[kk][0];
    #pragma unroll
    for (int i=0;i<4;i++){
      float4 f4; f4.x=kvv[4*i]*inv; f4.y=kvv[4*i+1]*inv; f4.z=kvv[4*i+2]*inv; f4.w=kvv[4*i+3]*inv;
      kd[i]=f4;
    }
    { const float4* vr = reinterpret_cast<const float4*>(v + ((size_t)bh*LPAD + tk)*DH);
      float4* vd = (float4*)&Vs[kk][0];
      #pragma unroll
      for (int i=0;i<4;i++) vd[i]=vr[i];
    }
    tks[kk]=tk;
  }
  __syncthreads();
  float m=-3.0e38f, l=0.f;
  ull acc2[8];
  #pragma unroll
  for (int f=0;f<8;f++) acc2[f]=0ull;
  int jbase = half << 6;
  #pragma unroll 2
  for (int jj=0;jj<64;jj++){
    int j = jbase + jj;
    const ulonglong2* kr = (const ulonglong2*)&Ks[j][0];
    ull d2 = 0ull;
    #pragma unroll
    for (int i=0;i<4;i++){
      ulonglong2 u = kr[i];
      fma2(d2, qv[2*i],   u.x);
      fma2(d2, qv[2*i+1], u.y);
    }
    float d = hsum2(d2) * 0.25f;                 // DH^-0.5
    if (tks[j]==tq) d = -50000.0f;               // SELF_ATTN_VAL
    if (d>m){
      float sc=__expf(m-d);
      l*=sc;
      ull sc2 = pack2(sc,sc);
      #pragma unroll
      for (int f=0;f<8;f++) mul2(acc2[f], acc2[f], sc2);
      m=d;
    }
    float p=__expf(d-m);
    l += p;
    ull p2 = pack2(p,p);
    const ulonglong2* vr = (const ulonglong2*)&Vs[j][0];
    #pragma unroll
    for (int i=0;i<4;i++){
      ulonglong2 u = vr[i];
      fma2(acc2[2*i],   p2, u.x);
      fma2(acc2[2*i+1], p2, u.y);
    }
  }
  if (half){
    Pm[qi]=m; Pl[qi]=l;
    float tmp[16];
    #pragma unroll
    for (int f=0;f<8;f++) unpack2(acc2[f], tmp[2*f], tmp[2*f+1]);
    float4* pa = (float4*)Pacc[qi];
    #pragma unroll
    for (int i=0;i<4;i++){
      float4 f4; f4.x=tmp[4*i]; f4.y=tmp[4*i+1]; f4.z=tmp[4*i+2]; f4.w=tmp[4*i+3];
      pa[i]=f4;
    }
  }
  __syncthreads();
  if (!half){
    float m2 = Pm[qi], l2 = Pl[qi];
    float M = fmaxf(m, m2);
    float s1 = __expf(m - M), s2 = __expf(m2 - M);
    float L = l*s1 + l2*s2;
    float invl = 1.0f/L;
    float out[16];
    #pragma unroll
    for (int f=0;f<8;f++) unpack2(acc2[f], out[2*f], out[2*f+1]);
    const float4* pa = (const float4*)Pacc[qi];
    float4* op = (float4*)(o + ((size_t)(bh*NR + rq)*LPAD + tq)*DH);  // scatter == undo_sort
    #pragma unroll
    for (int i=0;i<4;i++){
      float4 p = pa[i];
      float4 f4;
      f4.x = (out[4*i+0]*s1 + p.x*s2)*invl;
      f4.y = (out[4*i+1]*s1 + p.y*s2)*invl;
      f4.z = (out[4*i+2]*s1 + p.z*s2)*invl;
      f4.w = (out[4*i+3]*s1 + p.w*s2)*invl;
      op[i]=f4;
    }
    lse[(size_t)(bh*NR+rq)*LPAD + tq] = M + logf(L);
  }
}

// ---------------- final: y = ((x1+x2)*0.5) @ out_w + out_b, trim to 1250 ----------------
__global__ void k_final(const float* __restrict__ x1, const float* __restrict__ x2,
                        const float* __restrict__ ow, const float* __restrict__ ob,
                        float* __restrict__ y){
  int row  = blockIdx.x*4 + (threadIdx.x>>5);    // 16*1250 rows
  int lane = threadIdx.x & 31;
  int b = row / LIN, t = row % LIN;
  size_t base = ((size_t)b*LPAD + t)*DM;
  float s = (x1[base+lane]+x2[base+lane])*0.5f*ow[lane]
          + (x1[base+lane+32]+x2[base+lane+32])*0.5f*ow[lane+32];
  #pragma unroll
  for (int o2=16;o2>0;o2>>=1) s += __shfl_xor_sync(0xffffffffu, s, o2);
  if (lane==0) y[row] = s + ob[0];
}

// ---------------- host launcher ----------------
extern "C" void kernel_launch(void* const* d_in, const int* in_sizes, int n_in,
                              void* d_out, int out_size){
  const float* wave  = (const float*)d_in[0];
  const float* in_w  = (const float*)d_in[1];
  const float* in_b  = (const float*)d_in[2];
  const float* ln1_g = (const float*)d_in[3];
  const float* ln1_b = (const float*)d_in[4];
  const float* wqk   = (const float*)d_in[5];
  const float* wv    = (const float*)d_in[6];
  const float* wo_w  = (const float*)d_in[7];
  const float* wo_b  = (const float*)d_in[8];
  const float* rot   = (const float*)d_in[9];
  const float* ln2_g = (const float*)d_in[10];
  const float* ln2_b = (const float*)d_in[11];
  const float* w1    = (const float*)d_in[12];
  const float* b1    = (const float*)d_in[13];
  const float* w2    = (const float*)d_in[14];
  const float* b2    = (const float*)d_in[15];
  const float* out_w = (const float*)d_in[16];
  const float* out_b = (const float*)d_in[17];

  float *x1,*x2,*qkp,*vp,*op,*lsp,*ffp;
  unsigned char* bktp; int *cntp; short* sjp;
  cudaGetSymbolAddress((void**)&x1,  g_x1);
  cudaGetSymbolAddress((void**)&x2,  g_x2);
  cudaGetSymbolAddress((void**)&qkp, g_qk);
  cudaGetSymbolAddress((void**)&vp,  g_v);
  cudaGetSymbolAddress((void**)&bktp,g_bkt);
  cudaGetSymbolAddress((void**)&cntp,g_cnt);
  cudaGetSymbolAddress((void**)&sjp, g_sj);
  cudaGetSymbolAddress((void**)&op,  g_o);
  cudaGetSymbolAddress((void**)&lsp, g_lse);
  cudaGetSymbolAddress((void**)&ffp, g_ffh);

  const int LNQKV_SMEM = (64*68 + 2*4096)*sizeof(float);   // 50176 B
  cudaFuncSetAttribute(k_lnqkv, cudaFuncAttributeMaxDynamicSharedMemorySize, LNQKV_SMEM);

  k_embed<<<5120,256>>>(wave, in_w, in_b, x1, x2);

  for (int i=0;i<4;i++){
    k_lnqkv<<<320,256,LNQKV_SMEM>>>(x2, ln1_g+i*64, ln1_b+i*64,
                                    wqk+i*4096, wv+i*4096, qkp, vp);
    k_hashcount<<<dim3(8,64),160>>>(qkp, rot+i*640, bktp, cntp);
    k_psort<<<64,640>>>(cntp, bktp, sjp);
    k_attn<<<dim3(80,64),128>>>(qkp, vp, sjp, op, lsp);
    k_wo<<<320,256>>>(op, lsp, wo_w+i*4096, wo_b+i*64, x1);
    k_ff1<<<dim3(320,4),256>>>(x1, ln2_g+i*64, ln2_b+i*64, w1+i*16384, b1+i*256, ffp);
    k_ff2<<<320,256>>>(ffp, w2+i*16384, b2+i*64, x2);
  }

  k_final<<<5000,128>>>(x1, x2, out_w, out_b, (float*)d_out);
}